// round 9
// baseline (speedup 1.0000x reference)
#include <cuda_runtime.h>
#include <cuda_bf16.h>
#include <math.h>
#include <cstdint>

// ---------------------------------------------------------------------------
// SOMI settling layer — Paterson-Stockmeyer collapsed formulation.
//   N = |W|/deg - (1.1 + p) on diag;  H = (1-g)I + g*(D0 + N^4(D1 + N^4 D2))
//   out = H @ h over the hidden dim.
// Whole pipeline on mma.sync bf16 hi/lo split (hi*hi + hi*lo + lo*hi, fp32
// accumulate): 5x 512^3 GEMMs with fused epilogues + 1 big 16384x512x512.
//
// HARD RULES LEARNED:
//  R3/R4: never pass __device__ global symbols as host-side kernel args
//         (Grace ATS migrates pages -> harness allocation violation).
//  R6:    harness compiles to baseline sm_100 (NOT sm_100a) -> tcgen05/TMEM
//         PTX rejected. Only baseline ISA: mma.sync + ldmatrix.
//  R8:    container infra failure (kernel never ran) -> resubmitted unchanged.
// ---------------------------------------------------------------------------

#define DIM 512

// fp32 arena ids
#define BUF_N   0
#define BUF_N2  1
#define BUF_N3  2
#define BUF_D0  3
#define BUF_D1  4
// bf16 hi/lo arena ids
#define HB_N    0
#define HB_N2   1
#define HB_N4   2
#define HB_D2   3
#define HB_E    4
#define HB_H    5

__device__ __align__(16) float g_deg[DIM];
__device__ __align__(16) float g_buf[5][DIM * DIM];
__device__ __align__(16) __nv_bfloat16 g_bhi[6][DIM * DIM];
__device__ __align__(16) __nv_bfloat16 g_blo[6][DIM * DIM];

struct Coef { float P[3][4]; float Q[3][4]; };

// ======================= helpers ===========================================
__device__ __forceinline__ uint32_t smem_u32(const void* p) {
    uint32_t a;
    asm("{ .reg .u64 t; cvta.to.shared.u64 t, %1; cvt.u32.u64 %0, t; }"
        : "=r"(a) : "l"(p));
    return a;
}
__device__ __forceinline__ uint32_t bf2_pack(__nv_bfloat16 a, __nv_bfloat16 b) {
    __nv_bfloat162 t = __halves2bfloat162(a, b);
    return *reinterpret_cast<uint32_t*>(&t);
}
__device__ __forceinline__ void ldm_x4(uint32_t& r0, uint32_t& r1,
                                       uint32_t& r2, uint32_t& r3, uint32_t a) {
    asm volatile("ldmatrix.sync.aligned.m8n8.x4.shared.b16 {%0,%1,%2,%3}, [%4];"
                 : "=r"(r0), "=r"(r1), "=r"(r2), "=r"(r3) : "r"(a));
}
__device__ __forceinline__ void ldm_x2(uint32_t& r0, uint32_t& r1, uint32_t a) {
    asm volatile("ldmatrix.sync.aligned.m8n8.x2.shared.b16 {%0,%1}, [%2];"
                 : "=r"(r0), "=r"(r1) : "r"(a));
}
__device__ __forceinline__ void ldm_x2t(uint32_t& r0, uint32_t& r1, uint32_t a) {
    asm volatile("ldmatrix.sync.aligned.m8n8.x2.trans.shared.b16 {%0,%1}, [%2];"
                 : "=r"(r0), "=r"(r1) : "r"(a));
}
__device__ __forceinline__ void mma_bf16(float* c, const uint32_t* a,
                                         const uint32_t* b) {
    asm volatile(
        "mma.sync.aligned.m16n8k16.row.col.f32.bf16.bf16.f32 "
        "{%0,%1,%2,%3}, {%4,%5,%6,%7}, {%8,%9}, {%0,%1,%2,%3};"
        : "+f"(c[0]), "+f"(c[1]), "+f"(c[2]), "+f"(c[3])
        : "r"(a[0]), "r"(a[1]), "r"(a[2]), "r"(a[3]), "r"(b[0]), "r"(b[1]));
}
__device__ __forceinline__ void split_store(int hl, int off, float v0, float v1) {
    __nv_bfloat16 h0 = __float2bfloat16_rn(v0);
    __nv_bfloat16 h1 = __float2bfloat16_rn(v1);
    __nv_bfloat16 l0 = __float2bfloat16_rn(v0 - __bfloat162float(h0));
    __nv_bfloat16 l1 = __float2bfloat16_rn(v1 - __bfloat162float(h1));
    *(uint32_t*)&g_bhi[hl][off] = bf2_pack(h0, h1);
    *(uint32_t*)&g_blo[hl][off] = bf2_pack(l0, l1);
}

// ======================= build kernels =====================================
__global__ void build_deg(const float* __restrict__ W) {
    int warp = (blockIdx.x * blockDim.x + threadIdx.x) >> 5;
    int lane = threadIdx.x & 31;
    if (warp >= DIM) return;
    float s = 0.f;
    const float* row = W + (size_t)warp * DIM;
    for (int d = lane; d < DIM; d += 32) s += fabsf(row[d]);
    #pragma unroll
    for (int o = 16; o > 0; o >>= 1) s += __shfl_down_sync(0xffffffffu, s, o);
    if (lane == 0) g_deg[warp] = fmaxf(s, 1e-8f);
}

// N = |W|/deg - (1.1 + p) on diag; also emit hi/lo
__global__ void build_N(const float* __restrict__ W, const float* __restrict__ p) {
    int v = blockIdx.x * blockDim.x + threadIdx.x;   // element-pair index
    if (v >= DIM * DIM / 2) return;
    int idx = v * 2;
    int e = idx >> 9;
    int d = idx & (DIM - 1);
    float m0 = fabsf(W[idx]) / g_deg[e];
    float m1 = fabsf(W[idx + 1]) / g_deg[e];
    if (e == d)     m0 -= (1.1f + p[d]);
    if (e == d + 1) m1 -= (1.1f + p[d + 1]);
    g_buf[BUF_N][idx]     = m0;
    g_buf[BUF_N][idx + 1] = m1;
    split_store(HB_N, idx, m0, m1);
}

// D_j = P_j(N) + Q_j(N) * diag(p);  D0,D1 fp32; D2 hi/lo
__global__ __launch_bounds__(256)
void build_D(const float* __restrict__ p, Coef cf) {
    int v = blockIdx.x * blockDim.x + threadIdx.x;
    if (v >= DIM * DIM / 2) return;
    int idx = v * 2;
    int e = idx >> 9;
    int d = idx & (DIM - 1);

    float r[3][2];
    #pragma unroll
    for (int u = 0; u < 2; u++) {
        int dd = d + u;
        float x0 = (e == dd) ? 1.f : 0.f;
        float x1 = g_buf[BUF_N ][idx + u];
        float x2 = g_buf[BUF_N2][idx + u];
        float x3 = g_buf[BUF_N3][idx + u];
        float pd = p[dd];
        #pragma unroll
        for (int j = 0; j < 3; j++) {
            float vp = cf.P[j][0] * x0 + cf.P[j][1] * x1 + cf.P[j][2] * x2 + cf.P[j][3] * x3;
            float vq = cf.Q[j][0] * x0 + cf.Q[j][1] * x1 + cf.Q[j][2] * x2 + cf.Q[j][3] * x3;
            r[j][u] = vp + vq * pd;
        }
    }
    g_buf[BUF_D0][idx]     = r[0][0];
    g_buf[BUF_D0][idx + 1] = r[0][1];
    g_buf[BUF_D1][idx]     = r[1][0];
    g_buf[BUF_D1][idx + 1] = r[1][1];
    split_store(HB_D2, idx, r[2][0], r[2][1]);
}

// ======================= mma.sync 512^3 GEMM (fused epilogue) ==============
// C = A(hi/lo) @ B(hi/lo); CTA 64x64, grid 8x8, 8 warps (2x4), warp 32x16.
// A natural [m][k]; B natural [k][n] consumed via ldmatrix.trans.
// mode 0: C plain; 1: C += g_buf[addi]; 2: C = g*(C+g_buf[addi]) + (1-g)I.
// outfp >= 0 -> write fp32 arena; outhl >= 0 -> write hi/lo arena.
#define APAD 40
#define BPAD 72

__global__ __launch_bounds__(256, 1)
void mma512(int ahl, int bhl, int mode, int addi, int outfp, int outhl,
            const float* __restrict__ ga) {
    __shared__ __align__(16) uint16_t Ahi[64][APAD];
    __shared__ __align__(16) uint16_t Alo[64][APAD];
    __shared__ __align__(16) uint16_t Bhi[32][BPAD];
    __shared__ __align__(16) uint16_t Blo[32][BPAD];

    const int tid  = threadIdx.x;
    const int wid  = tid >> 5;
    const int lane = tid & 31;
    const int wr = wid & 1;         // m-half (32 rows)
    const int wc = wid >> 1;        // n-quarter (16 cols)
    const int brow = blockIdx.x * 64;
    const int bcol = blockIdx.y * 64;

    const __nv_bfloat16* __restrict__ Ah = g_bhi[ahl];
    const __nv_bfloat16* __restrict__ Al = g_blo[ahl];
    const __nv_bfloat16* __restrict__ Bh = g_bhi[bhl];
    const __nv_bfloat16* __restrict__ Bl = g_blo[bhl];

    float acc[2][2][4];
    #pragma unroll
    for (int i = 0; i < 2; i++)
        #pragma unroll
        for (int j = 0; j < 2; j++)
            #pragma unroll
            for (int q = 0; q < 4; q++) acc[i][j][q] = 0.f;

    const uint32_t ahB = smem_u32(&Ahi[0][0]);
    const uint32_t alB = smem_u32(&Alo[0][0]);
    const uint32_t bhB = smem_u32(&Bhi[0][0]);
    const uint32_t blB = smem_u32(&Blo[0][0]);
    const int aRow = wr * 32 + (lane & 15);
    const int aKp  = (lane >> 4) * 8;
    const int bLn  = lane & 15;      // k-row for trans load

    // loader lanes: A rows 64 x 32k (tid>>2, tid&3); B rows 32k x 64n (tid>>3, tid&7)
    const int lar = tid >> 2, laq = tid & 3;
    const int lbr = tid >> 3, lbq = tid & 7;

    for (int ch = 0; ch < 16; ch++) {
        const int k0 = ch * 32;
        *(uint4*)&Ahi[lar][laq * 8] = *(const uint4*)&Ah[(size_t)(brow + lar) * DIM + k0 + laq * 8];
        *(uint4*)&Alo[lar][laq * 8] = *(const uint4*)&Al[(size_t)(brow + lar) * DIM + k0 + laq * 8];
        *(uint4*)&Bhi[lbr][lbq * 8] = *(const uint4*)&Bh[(size_t)(k0 + lbr) * DIM + bcol + lbq * 8];
        *(uint4*)&Blo[lbr][lbq * 8] = *(const uint4*)&Bl[(size_t)(k0 + lbr) * DIM + bcol + lbq * 8];
        __syncthreads();

        #pragma unroll
        for (int ks = 0; ks < 2; ks++) {
            const int kk = ks * 16;
            uint32_t ah[2][4], al[2][4], bh[2][2], bl[2][2];
            #pragma unroll
            for (int mt = 0; mt < 2; mt++) {
                uint32_t ao = ((uint32_t)((aRow + mt * 16) * APAD + kk + aKp)) * 2;
                ldm_x4(ah[mt][0], ah[mt][1], ah[mt][2], ah[mt][3], ahB + ao);
                ldm_x4(al[mt][0], al[mt][1], al[mt][2], al[mt][3], alB + ao);
            }
            #pragma unroll
            for (int nt = 0; nt < 2; nt++) {
                uint32_t bo = ((uint32_t)((kk + bLn) * BPAD + wc * 16 + nt * 8)) * 2;
                ldm_x2t(bh[nt][0], bh[nt][1], bhB + bo);
                ldm_x2t(bl[nt][0], bl[nt][1], blB + bo);
            }
            #pragma unroll
            for (int mt = 0; mt < 2; mt++)
                #pragma unroll
                for (int nt = 0; nt < 2; nt++) {
                    mma_bf16(acc[mt][nt], ah[mt], bh[nt]);
                    mma_bf16(acc[mt][nt], ah[mt], bl[nt]);
                    mma_bf16(acc[mt][nt], al[mt], bh[nt]);
                }
        }
        __syncthreads();
    }

    // fused epilogue
    const float g = (mode == 2) ? tanhf(ga[0]) : 0.f;
    const float omg = 1.0f - g;
    const int er0 = brow + wr * 32 + (lane >> 2);
    const int ec0 = bcol + wc * 16 + (lane & 3) * 2;

    #pragma unroll
    for (int mt = 0; mt < 2; mt++) {
        #pragma unroll
        for (int nt = 0; nt < 2; nt++) {
            #pragma unroll
            for (int half = 0; half < 2; half++) {
                int r = er0 + mt * 16 + half * 8;
                int c = ec0 + nt * 8;
                int off = r * DIM + c;
                float v0 = acc[mt][nt][half * 2 + 0];
                float v1 = acc[mt][nt][half * 2 + 1];
                if (mode == 1) {
                    v0 += g_buf[addi][off];
                    v1 += g_buf[addi][off + 1];
                } else if (mode == 2) {
                    v0 = g * (v0 + g_buf[addi][off])     + ((r == c)     ? omg : 0.f);
                    v1 = g * (v1 + g_buf[addi][off + 1]) + ((r == c + 1) ? omg : 0.f);
                }
                if (outfp >= 0) *(float2*)&g_buf[outfp][off] = make_float2(v0, v1);
                if (outhl >= 0) split_store(outhl, off, v0, v1);
            }
        }
    }
}

// ======================= mma.sync big GEMM (proven R7) =====================
// out[r, e] = sum_d h[r, d] * H[e, d];  H read from hi/lo arena id HB_H.
__global__ __launch_bounds__(256, 1)
void mma_gemm(const float* __restrict__ h, float* __restrict__ out) {
    __shared__ __align__(16) uint16_t Ahi[128][APAD];
    __shared__ __align__(16) uint16_t Alo[128][APAD];
    __shared__ __align__(16) uint16_t Bhi[128][APAD];
    __shared__ __align__(16) uint16_t Blo[128][APAD];

    const int tid  = threadIdx.x;
    const int wid  = tid >> 5;
    const int lane = tid & 31;
    const int wr = wid & 1;
    const int wc = wid >> 1;
    const int brow = blockIdx.x * 128;
    const int bcol = blockIdx.y * 128;

    const __nv_bfloat16* __restrict__ Hh = g_bhi[HB_H];
    const __nv_bfloat16* __restrict__ Hl = g_blo[HB_H];

    float acc[4][4][4];
    #pragma unroll
    for (int i = 0; i < 4; i++)
        #pragma unroll
        for (int j = 0; j < 4; j++)
            #pragma unroll
            for (int q = 0; q < 4; q++) acc[i][j][q] = 0.f;

    const uint32_t aBase  = smem_u32(&Ahi[0][0]);
    const uint32_t alBase = smem_u32(&Alo[0][0]);
    const uint32_t bBase  = smem_u32(&Bhi[0][0]);
    const uint32_t blBase = smem_u32(&Blo[0][0]);
    const int aRow = wr * 64 + (lane & 15);
    const int aKp  = (lane >> 4) * 8;
    const int bRow = wc * 32 + (lane & 7);
    const int bKp  = ((lane >> 3) & 1) * 8;

    for (int ch = 0; ch < 16; ch++) {
        const int k0 = ch * 32;
        #pragma unroll
        for (int i = 0; i < 4; i++) {
            int t = tid + i * 256;
            int row = t >> 3;
            int q   = t & 7;
            float4 v = *(const float4*)&h[(size_t)(brow + row) * DIM + k0 + q * 4];
            __nv_bfloat16 hx = __float2bfloat16_rn(v.x);
            __nv_bfloat16 hy = __float2bfloat16_rn(v.y);
            __nv_bfloat16 hz = __float2bfloat16_rn(v.z);
            __nv_bfloat16 hw = __float2bfloat16_rn(v.w);
            __nv_bfloat16 lx = __float2bfloat16_rn(v.x - __bfloat162float(hx));
            __nv_bfloat16 ly = __float2bfloat16_rn(v.y - __bfloat162float(hy));
            __nv_bfloat16 lz = __float2bfloat16_rn(v.z - __bfloat162float(hz));
            __nv_bfloat16 lw = __float2bfloat16_rn(v.w - __bfloat162float(hw));
            *(uint2*)&Ahi[row][q * 4] = make_uint2(bf2_pack(hx, hy), bf2_pack(hz, hw));
            *(uint2*)&Alo[row][q * 4] = make_uint2(bf2_pack(lx, ly), bf2_pack(lz, lw));
        }
        #pragma unroll
        for (int i = 0; i < 2; i++) {
            int t = tid + i * 256;
            int row = t >> 2;
            int q   = t & 3;
            *(uint4*)&Bhi[row][q * 8] = *(const uint4*)&Hh[(size_t)(bcol + row) * DIM + k0 + q * 8];
            *(uint4*)&Blo[row][q * 8] = *(const uint4*)&Hl[(size_t)(bcol + row) * DIM + k0 + q * 8];
        }
        __syncthreads();

        #pragma unroll
        for (int ks = 0; ks < 2; ks++) {
            const int kk = ks * 16;
            uint32_t ah[4][4], al[4][4], bh[4][2], bl[4][2];
            #pragma unroll
            for (int mt = 0; mt < 4; mt++) {
                uint32_t ao = ((uint32_t)((aRow + mt * 16) * APAD + kk + aKp)) * 2;
                ldm_x4(ah[mt][0], ah[mt][1], ah[mt][2], ah[mt][3], aBase + ao);
                ldm_x4(al[mt][0], al[mt][1], al[mt][2], al[mt][3], alBase + ao);
            }
            #pragma unroll
            for (int nt = 0; nt < 4; nt++) {
                uint32_t bo = ((uint32_t)((bRow + nt * 8) * APAD + kk + bKp)) * 2;
                ldm_x2(bh[nt][0], bh[nt][1], bBase + bo);
                ldm_x2(bl[nt][0], bl[nt][1], blBase + bo);
            }
            #pragma unroll
            for (int mt = 0; mt < 4; mt++)
                #pragma unroll
                for (int nt = 0; nt < 4; nt++) {
                    mma_bf16(acc[mt][nt], ah[mt], bh[nt]);
                    mma_bf16(acc[mt][nt], ah[mt], bl[nt]);
                    mma_bf16(acc[mt][nt], al[mt], bh[nt]);
                }
        }
        __syncthreads();
    }

    const int er = brow + wr * 64 + (lane >> 2);
    const int ec = bcol + wc * 32 + (lane & 3) * 2;
    #pragma unroll
    for (int mt = 0; mt < 4; mt++) {
        #pragma unroll
        for (int nt = 0; nt < 4; nt++) {
            float* p0 = out + (size_t)(er + mt * 16) * DIM + ec + nt * 8;
            *(float2*)p0 = make_float2(acc[mt][nt][0], acc[mt][nt][1]);
            float* p1 = out + (size_t)(er + mt * 16 + 8) * DIM + ec + nt * 8;
            *(float2*)p1 = make_float2(acc[mt][nt][2], acc[mt][nt][3]);
        }
    }
}

// ---------------------------------------------------------------------------
extern "C" void kernel_launch(void* const* d_in, const int* in_sizes, int n_in,
                              void* d_out, int out_size) {
    const float* h  = (const float*)d_in[0];  // hidden_states [B,S,D]
    const float* W  = (const float*)d_in[1];  // [D,D]
    const float* ga = (const float*)d_in[2];  // gate_alpha [1]
    const float* p  = (const float*)d_in[3];  // precision [D]
    float* out = (float*)d_out;

    const int R = in_sizes[0] / DIM;          // B*S = 16384

    // host-side polynomial coefficients (doubles; deterministic)
    double Ac[12] = {0}, Bc[12] = {0}, Cc[12] = {0}, Dc[12] = {0};
    Ac[0] = 1.0;
    {
        const double dt = 0.1, beta = 2.0 * sqrt(2.1), c1 = 1.0 - dt * beta;
        for (int n = 0; n < 10; n++) {
            double Cn[12], Dn[12];
            for (int k = 0; k < 12; k++) {
                Cn[k] = c1 * Cc[k] + (k > 0 ? dt * Ac[k - 1] : 0.0);
                Dn[k] = c1 * Dc[k] + (k > 0 ? dt * Bc[k - 1] : 0.0);
            }
            Dn[0] += dt;
            for (int k = 0; k < 12; k++) {
                Cc[k] = Cn[k];  Dc[k] = Dn[k];
                Ac[k] += dt * Cn[k];
                Bc[k] += dt * Dn[k];
            }
        }
    }
    Coef cf;
    for (int j = 0; j < 3; j++)
        for (int m = 0; m < 4; m++) {
            cf.P[j][m] = (float)Ac[4 * j + m];
            cf.Q[j][m] = (float)Bc[4 * j + m];
        }

    const int PAIR_BLKS = (DIM * DIM / 2 + 255) / 256;
    const dim3 G512(8, 8);

    build_deg<<<(DIM * 32 + 255) / 256, 256>>>(W);
    build_N<<<PAIR_BLKS, 256>>>(W, p);

    // N2 = N*N           (fp32 for build_D + hi/lo operand)
    mma512<<<G512, 256>>>(HB_N,  HB_N,  0, 0, BUF_N2, HB_N2, ga);
    // N3 = N*N2          (fp32 for build_D only)
    mma512<<<G512, 256>>>(HB_N,  HB_N2, 0, 0, BUF_N3, -1,    ga);
    // N4 = N2*N2         (hi/lo operand only)
    mma512<<<G512, 256>>>(HB_N2, HB_N2, 0, 0, -1,     HB_N4, ga);

    build_D<<<PAIR_BLKS, 256>>>(p, cf);

    // E = N4*D2 + D1     (hi/lo operand only)
    mma512<<<G512, 256>>>(HB_N4, HB_D2, 1, BUF_D1, -1, HB_E, ga);
    // H = g*(N4*E + D0) + (1-g)I   (hi/lo operand for the big GEMM)
    mma512<<<G512, 256>>>(HB_N4, HB_E,  2, BUF_D0, -1, HB_H, ga);

    mma_gemm<<<dim3(R / 128, DIM / 128), 256>>>(h, out);
}

// round 10
// speedup vs baseline: 1.2502x; 1.2502x over previous
#include <cuda_runtime.h>
#include <cuda_bf16.h>
#include <math.h>
#include <cstdint>

// ---------------------------------------------------------------------------
// SOMI settling layer — Paterson-Stockmeyer collapsed formulation.
//   N = |W|/deg - (1.1 + p) on diag;  H = (1-g)I + g*(D0 + N^4(D1 + N^4 D2))
//   out = H @ h over the hidden dim.
// All GEMMs on mma.sync bf16 hi/lo split (hi*hi + hi*lo + lo*hi, fp32 accum),
// cp.async double-buffered pipelines.
//
// HARD RULES LEARNED:
//  R3/R4: never pass __device__ global symbols as host-side kernel args.
//  R6:    harness compiles baseline sm_100 -> no tcgen05/TMEM; mma.sync only.
//  R9:    single-buffered smem mma loops are ~90% stalled -> cp.async pipeline.
// ---------------------------------------------------------------------------

#define DIM 512
#define RMAX (4 * 4096)

// fp32 arena ids
#define BUF_N   0
#define BUF_N2  1
#define BUF_N3  2
#define BUF_D0  3
#define BUF_D1  4
// bf16 hi/lo arena ids
#define HB_N    0
#define HB_N2   1
#define HB_N4   2
#define HB_D2   3
#define HB_E    4
#define HB_H    5

__device__ __align__(16) float g_deg[DIM];
__device__ __align__(16) float g_buf[5][DIM * DIM];
__device__ __align__(16) __nv_bfloat16 g_bhi[6][DIM * DIM];
__device__ __align__(16) __nv_bfloat16 g_blo[6][DIM * DIM];
__device__ __align__(16) __nv_bfloat16 g_hhi[RMAX * DIM];
__device__ __align__(16) __nv_bfloat16 g_hlo[RMAX * DIM];

struct Coef { float P[3][4]; float Q[3][4]; };
struct Job  { int ahl, bhl, mode, addi, outfp, outhl; };

// ======================= helpers ===========================================
__device__ __forceinline__ uint32_t smem_u32(const void* p) {
    uint32_t a;
    asm("{ .reg .u64 t; cvta.to.shared.u64 t, %1; cvt.u32.u64 %0, t; }"
        : "=r"(a) : "l"(p));
    return a;
}
__device__ __forceinline__ uint32_t bf2_pack(__nv_bfloat16 a, __nv_bfloat16 b) {
    __nv_bfloat162 t = __halves2bfloat162(a, b);
    return *reinterpret_cast<uint32_t*>(&t);
}
__device__ __forceinline__ void cp16(uint32_t dst, const void* src) {
    asm volatile("cp.async.cg.shared.global [%0], [%1], 16;"
                 :: "r"(dst), "l"(src) : "memory");
}
#define CP_COMMIT() asm volatile("cp.async.commit_group;" ::: "memory")
#define CP_WAIT1()  asm volatile("cp.async.wait_group 1;" ::: "memory")
#define CP_WAIT0()  asm volatile("cp.async.wait_group 0;" ::: "memory")

__device__ __forceinline__ void ldm_x4(uint32_t& r0, uint32_t& r1,
                                       uint32_t& r2, uint32_t& r3, uint32_t a) {
    asm volatile("ldmatrix.sync.aligned.m8n8.x4.shared.b16 {%0,%1,%2,%3}, [%4];"
                 : "=r"(r0), "=r"(r1), "=r"(r2), "=r"(r3) : "r"(a));
}
__device__ __forceinline__ void ldm_x2(uint32_t& r0, uint32_t& r1, uint32_t a) {
    asm volatile("ldmatrix.sync.aligned.m8n8.x2.shared.b16 {%0,%1}, [%2];"
                 : "=r"(r0), "=r"(r1) : "r"(a));
}
__device__ __forceinline__ void ldm_x2t(uint32_t& r0, uint32_t& r1, uint32_t a) {
    asm volatile("ldmatrix.sync.aligned.m8n8.x2.trans.shared.b16 {%0,%1}, [%2];"
                 : "=r"(r0), "=r"(r1) : "r"(a));
}
__device__ __forceinline__ void mma_bf16(float* c, const uint32_t* a,
                                         const uint32_t* b) {
    asm volatile(
        "mma.sync.aligned.m16n8k16.row.col.f32.bf16.bf16.f32 "
        "{%0,%1,%2,%3}, {%4,%5,%6,%7}, {%8,%9}, {%0,%1,%2,%3};"
        : "+f"(c[0]), "+f"(c[1]), "+f"(c[2]), "+f"(c[3])
        : "r"(a[0]), "r"(a[1]), "r"(a[2]), "r"(a[3]), "r"(b[0]), "r"(b[1]));
}
__device__ __forceinline__ void split_store(int hl, int off, float v0, float v1) {
    __nv_bfloat16 h0 = __float2bfloat16_rn(v0);
    __nv_bfloat16 h1 = __float2bfloat16_rn(v1);
    __nv_bfloat16 l0 = __float2bfloat16_rn(v0 - __bfloat162float(h0));
    __nv_bfloat16 l1 = __float2bfloat16_rn(v1 - __bfloat162float(h1));
    *(uint32_t*)&g_bhi[hl][off] = bf2_pack(h0, h1);
    *(uint32_t*)&g_blo[hl][off] = bf2_pack(l0, l1);
}

// ======================= build kernels =====================================
__global__ void build_deg(const float* __restrict__ W) {
    int warp = (blockIdx.x * blockDim.x + threadIdx.x) >> 5;
    int lane = threadIdx.x & 31;
    if (warp >= DIM) return;
    float s = 0.f;
    const float* row = W + (size_t)warp * DIM;
    for (int d = lane; d < DIM; d += 32) s += fabsf(row[d]);
    #pragma unroll
    for (int o = 16; o > 0; o >>= 1) s += __shfl_down_sync(0xffffffffu, s, o);
    if (lane == 0) g_deg[warp] = fmaxf(s, 1e-8f);
}

__global__ void build_N(const float* __restrict__ W, const float* __restrict__ p) {
    int v = blockIdx.x * blockDim.x + threadIdx.x;
    if (v >= DIM * DIM / 2) return;
    int idx = v * 2;
    int e = idx >> 9;
    int d = idx & (DIM - 1);
    float m0 = fabsf(W[idx]) / g_deg[e];
    float m1 = fabsf(W[idx + 1]) / g_deg[e];
    if (e == d)     m0 -= (1.1f + p[d]);
    if (e == d + 1) m1 -= (1.1f + p[d + 1]);
    g_buf[BUF_N][idx]     = m0;
    g_buf[BUF_N][idx + 1] = m1;
    split_store(HB_N, idx, m0, m1);
}

// h (fp32) -> bf16 hi/lo global buffers (read once by the big GEMM)
__global__ void split_h(const float* __restrict__ h, int nvec) {
    int v = blockIdx.x * blockDim.x + threadIdx.x;   // float4 index
    if (v >= nvec) return;
    float4 x = ((const float4*)h)[v];
    int idx = v * 4;
    __nv_bfloat16 h0 = __float2bfloat16_rn(x.x);
    __nv_bfloat16 h1 = __float2bfloat16_rn(x.y);
    __nv_bfloat16 h2 = __float2bfloat16_rn(x.z);
    __nv_bfloat16 h3 = __float2bfloat16_rn(x.w);
    __nv_bfloat16 l0 = __float2bfloat16_rn(x.x - __bfloat162float(h0));
    __nv_bfloat16 l1 = __float2bfloat16_rn(x.y - __bfloat162float(h1));
    __nv_bfloat16 l2 = __float2bfloat16_rn(x.z - __bfloat162float(h2));
    __nv_bfloat16 l3 = __float2bfloat16_rn(x.w - __bfloat162float(h3));
    *(uint2*)&g_hhi[idx] = make_uint2(bf2_pack(h0, h1), bf2_pack(h2, h3));
    *(uint2*)&g_hlo[idx] = make_uint2(bf2_pack(l0, l1), bf2_pack(l2, l3));
}

__global__ __launch_bounds__(256)
void build_D(const float* __restrict__ p, Coef cf) {
    int v = blockIdx.x * blockDim.x + threadIdx.x;
    if (v >= DIM * DIM / 2) return;
    int idx = v * 2;
    int e = idx >> 9;
    int d = idx & (DIM - 1);
    float r[3][2];
    #pragma unroll
    for (int u = 0; u < 2; u++) {
        int dd = d + u;
        float x0 = (e == dd) ? 1.f : 0.f;
        float x1 = g_buf[BUF_N ][idx + u];
        float x2 = g_buf[BUF_N2][idx + u];
        float x3 = g_buf[BUF_N3][idx + u];
        float pd = p[dd];
        #pragma unroll
        for (int j = 0; j < 3; j++) {
            float vp = cf.P[j][0] * x0 + cf.P[j][1] * x1 + cf.P[j][2] * x2 + cf.P[j][3] * x3;
            float vq = cf.Q[j][0] * x0 + cf.Q[j][1] * x1 + cf.Q[j][2] * x2 + cf.Q[j][3] * x3;
            r[j][u] = vp + vq * pd;
        }
    }
    g_buf[BUF_D0][idx]     = r[0][0];
    g_buf[BUF_D0][idx + 1] = r[0][1];
    g_buf[BUF_D1][idx]     = r[1][0];
    g_buf[BUF_D1][idx + 1] = r[1][1];
    split_store(HB_D2, idx, r[2][0], r[2][1]);
}

// ======================= mma.sync 512^3 GEMM (cp.async pipelined) ==========
// C = A(hi/lo) @ B(hi/lo); CTA 64x64, grid (8,8,z), 8 warps, warp 32x16.
// blockIdx.z selects job j0/j1 (merged independent GEMMs).
// mode 0: plain; 1: += g_buf[addi]; 2: g*(C+g_buf[addi]) + (1-g)I.
#define APAD 40
#define BPAD 72

__global__ __launch_bounds__(256, 1)
void mma512(Job j0, Job j1, const float* __restrict__ ga) {
    __shared__ __align__(16) uint16_t Ahi[2][64][APAD];
    __shared__ __align__(16) uint16_t Alo[2][64][APAD];
    __shared__ __align__(16) uint16_t Bhi[2][32][BPAD];
    __shared__ __align__(16) uint16_t Blo[2][32][BPAD];

    const Job j = (blockIdx.z == 0) ? j0 : j1;
    const int tid  = threadIdx.x;
    const int wid  = tid >> 5;
    const int lane = tid & 31;
    const int wr = wid & 1;
    const int wc = wid >> 1;
    const int brow = blockIdx.x * 64;
    const int bcol = blockIdx.y * 64;

    const __nv_bfloat16* __restrict__ Ah = g_bhi[j.ahl];
    const __nv_bfloat16* __restrict__ Al = g_blo[j.ahl];
    const __nv_bfloat16* __restrict__ Bh = g_bhi[j.bhl];
    const __nv_bfloat16* __restrict__ Bl = g_blo[j.bhl];

    float acc[2][2][4];
    #pragma unroll
    for (int i = 0; i < 2; i++)
        #pragma unroll
        for (int jj = 0; jj < 2; jj++)
            #pragma unroll
            for (int q = 0; q < 4; q++) acc[i][jj][q] = 0.f;

    const int aRow = wr * 32 + (lane & 15);
    const int aKp  = (lane >> 4) * 8;
    const int bLn  = lane & 15;
    const int lar = tid >> 2, laq = tid & 3;   // A: 64 rows x 4 16B-chunks
    const int lbr = tid >> 3, lbq = tid & 7;   // B: 32 rows x 8 16B-chunks

    // prologue: chunk 0 -> buffer 0
    cp16(smem_u32(&Ahi[0][lar][laq * 8]), &Ah[(size_t)(brow + lar) * DIM + laq * 8]);
    cp16(smem_u32(&Alo[0][lar][laq * 8]), &Al[(size_t)(brow + lar) * DIM + laq * 8]);
    cp16(smem_u32(&Bhi[0][lbr][lbq * 8]), &Bh[(size_t)lbr * DIM + bcol + lbq * 8]);
    cp16(smem_u32(&Blo[0][lbr][lbq * 8]), &Bl[(size_t)lbr * DIM + bcol + lbq * 8]);
    CP_COMMIT();

    for (int ch = 0; ch < 16; ch++) {
        if (ch + 1 < 16) {
            const int nb = (ch + 1) & 1;
            const int nk = (ch + 1) * 32;
            cp16(smem_u32(&Ahi[nb][lar][laq * 8]), &Ah[(size_t)(brow + lar) * DIM + nk + laq * 8]);
            cp16(smem_u32(&Alo[nb][lar][laq * 8]), &Al[(size_t)(brow + lar) * DIM + nk + laq * 8]);
            cp16(smem_u32(&Bhi[nb][lbr][lbq * 8]), &Bh[(size_t)(nk + lbr) * DIM + bcol + lbq * 8]);
            cp16(smem_u32(&Blo[nb][lbr][lbq * 8]), &Bl[(size_t)(nk + lbr) * DIM + bcol + lbq * 8]);
            CP_COMMIT();
            CP_WAIT1();
        } else {
            CP_WAIT0();
        }
        __syncthreads();

        const int pb = ch & 1;
        const uint32_t ahB = smem_u32(&Ahi[pb][0][0]);
        const uint32_t alB = smem_u32(&Alo[pb][0][0]);
        const uint32_t bhB = smem_u32(&Bhi[pb][0][0]);
        const uint32_t blB = smem_u32(&Blo[pb][0][0]);

        #pragma unroll
        for (int ks = 0; ks < 2; ks++) {
            const int kk = ks * 16;
            uint32_t ah[2][4], al[2][4], bh[2][2], bl[2][2];
            #pragma unroll
            for (int mt = 0; mt < 2; mt++) {
                uint32_t ao = ((uint32_t)((aRow + mt * 16) * APAD + kk + aKp)) * 2;
                ldm_x4(ah[mt][0], ah[mt][1], ah[mt][2], ah[mt][3], ahB + ao);
                ldm_x4(al[mt][0], al[mt][1], al[mt][2], al[mt][3], alB + ao);
            }
            #pragma unroll
            for (int nt = 0; nt < 2; nt++) {
                uint32_t bo = ((uint32_t)((kk + bLn) * BPAD + wc * 16 + nt * 8)) * 2;
                ldm_x2t(bh[nt][0], bh[nt][1], bhB + bo);
                ldm_x2t(bl[nt][0], bl[nt][1], blB + bo);
            }
            #pragma unroll
            for (int mt = 0; mt < 2; mt++)
                #pragma unroll
                for (int nt = 0; nt < 2; nt++) {
                    mma_bf16(acc[mt][nt], ah[mt], bh[nt]);
                    mma_bf16(acc[mt][nt], ah[mt], bl[nt]);
                    mma_bf16(acc[mt][nt], al[mt], bh[nt]);
                }
        }
        __syncthreads();
    }

    const float g = (j.mode == 2) ? tanhf(ga[0]) : 0.f;
    const float omg = 1.0f - g;
    const int er0 = brow + wr * 32 + (lane >> 2);
    const int ec0 = bcol + wc * 16 + (lane & 3) * 2;

    #pragma unroll
    for (int mt = 0; mt < 2; mt++) {
        #pragma unroll
        for (int nt = 0; nt < 2; nt++) {
            #pragma unroll
            for (int half = 0; half < 2; half++) {
                int r = er0 + mt * 16 + half * 8;
                int c = ec0 + nt * 8;
                int off = r * DIM + c;
                float v0 = acc[mt][nt][half * 2 + 0];
                float v1 = acc[mt][nt][half * 2 + 1];
                if (j.mode == 1) {
                    v0 += g_buf[j.addi][off];
                    v1 += g_buf[j.addi][off + 1];
                } else if (j.mode == 2) {
                    v0 = g * (v0 + g_buf[j.addi][off])     + ((r == c)     ? omg : 0.f);
                    v1 = g * (v1 + g_buf[j.addi][off + 1]) + ((r == c + 1) ? omg : 0.f);
                }
                if (j.outfp >= 0) *(float2*)&g_buf[j.outfp][off] = make_float2(v0, v1);
                if (j.outhl >= 0) split_store(j.outhl, off, v0, v1);
            }
        }
    }
}

// ======================= big GEMM (cp.async pipelined, dyn smem) ===========
// out[r, e] = sum_d h[r, d] * H[e, d]; A from g_hhi/g_hlo, B from HB_H.
// CTA 128x128, grid (R/128, 4), 8 warps (2x4), warp 64x32; BK=32 chunks.
#define MG_BUF  40960
#define MG_AHI  0
#define MG_ALO  10240
#define MG_BHI  20480
#define MG_BLO  30720

__global__ __launch_bounds__(256)
void mma_gemm2(float* __restrict__ out) {
    extern __shared__ char dsm[];
    const uint32_t sb = smem_u32(dsm);

    const int tid  = threadIdx.x;
    const int wid  = tid >> 5;
    const int lane = tid & 31;
    const int wr = wid & 1;
    const int wc = wid >> 1;
    const int brow = blockIdx.x * 128;
    const int bcol = blockIdx.y * 128;

    const __nv_bfloat16* __restrict__ Hh = g_bhi[HB_H];
    const __nv_bfloat16* __restrict__ Hl = g_blo[HB_H];

    float acc[4][4][4];
    #pragma unroll
    for (int i = 0; i < 4; i++)
        #pragma unroll
        for (int jj = 0; jj < 4; jj++)
            #pragma unroll
            for (int q = 0; q < 4; q++) acc[i][jj][q] = 0.f;

    const int aRow = wr * 64 + (lane & 15);
    const int aKp  = (lane >> 4) * 8;
    const int bRow = wc * 32 + (lane & 7);
    const int bKp  = ((lane >> 3) & 1) * 8;
    const int lr0 = tid >> 2, lq0 = tid & 3;   // +64 rows for second iter

    // prologue: chunk 0 -> buffer 0
    #pragma unroll
    for (int i = 0; i < 2; i++) {
        int row = lr0 + i * 64;
        uint32_t d0 = sb + (uint32_t)(row * 80 + lq0 * 16);
        cp16(d0 + MG_AHI, &g_hhi[(size_t)(brow + row) * DIM + lq0 * 8]);
        cp16(d0 + MG_ALO, &g_hlo[(size_t)(brow + row) * DIM + lq0 * 8]);
        cp16(d0 + MG_BHI, &Hh[(size_t)(bcol + row) * DIM + lq0 * 8]);
        cp16(d0 + MG_BLO, &Hl[(size_t)(bcol + row) * DIM + lq0 * 8]);
    }
    CP_COMMIT();

    for (int ch = 0; ch < 16; ch++) {
        if (ch + 1 < 16) {
            const int nb = (ch + 1) & 1;
            const int nk = (ch + 1) * 32;
            #pragma unroll
            for (int i = 0; i < 2; i++) {
                int row = lr0 + i * 64;
                uint32_t d0 = sb + (uint32_t)(nb * MG_BUF + row * 80 + lq0 * 16);
                cp16(d0 + MG_AHI, &g_hhi[(size_t)(brow + row) * DIM + nk + lq0 * 8]);
                cp16(d0 + MG_ALO, &g_hlo[(size_t)(brow + row) * DIM + nk + lq0 * 8]);
                cp16(d0 + MG_BHI, &Hh[(size_t)(bcol + row) * DIM + nk + lq0 * 8]);
                cp16(d0 + MG_BLO, &Hl[(size_t)(bcol + row) * DIM + nk + lq0 * 8]);
            }
            CP_COMMIT();
            CP_WAIT1();
        } else {
            CP_WAIT0();
        }
        __syncthreads();

        const uint32_t bufb = sb + (uint32_t)((ch & 1) * MG_BUF);
        #pragma unroll
        for (int ks = 0; ks < 2; ks++) {
            const int kk = ks * 16;
            uint32_t ah[4][4], al[4][4], bh[4][2], bl[4][2];
            #pragma unroll
            for (int mt = 0; mt < 4; mt++) {
                uint32_t ao = ((uint32_t)((aRow + mt * 16) * APAD + kk + aKp)) * 2;
                ldm_x4(ah[mt][0], ah[mt][1], ah[mt][2], ah[mt][3], bufb + MG_AHI + ao);
                ldm_x4(al[mt][0], al[mt][1], al[mt][2], al[mt][3], bufb + MG_ALO + ao);
            }
            #pragma unroll
            for (int nt = 0; nt < 4; nt++) {
                uint32_t bo = ((uint32_t)((bRow + nt * 8) * APAD + kk + bKp)) * 2;
                ldm_x2(bh[nt][0], bh[nt][1], bufb + MG_BHI + bo);
                ldm_x2(bl[nt][0], bl[nt][1], bufb + MG_BLO + bo);
            }
            #pragma unroll
            for (int mt = 0; mt < 4; mt++)
                #pragma unroll
                for (int nt = 0; nt < 4; nt++) {
                    mma_bf16(acc[mt][nt], ah[mt], bh[nt]);
                    mma_bf16(acc[mt][nt], ah[mt], bl[nt]);
                    mma_bf16(acc[mt][nt], al[mt], bh[nt]);
                }
        }
        __syncthreads();
    }

    const int er = brow + wr * 64 + (lane >> 2);
    const int ec = bcol + wc * 32 + (lane & 3) * 2;
    #pragma unroll
    for (int mt = 0; mt < 4; mt++) {
        #pragma unroll
        for (int nt = 0; nt < 4; nt++) {
            float* p0 = out + (size_t)(er + mt * 16) * DIM + ec + nt * 8;
            *(float2*)p0 = make_float2(acc[mt][nt][0], acc[mt][nt][1]);
            float* p1 = out + (size_t)(er + mt * 16 + 8) * DIM + ec + nt * 8;
            *(float2*)p1 = make_float2(acc[mt][nt][2], acc[mt][nt][3]);
        }
    }
}

// ---------------------------------------------------------------------------
extern "C" void kernel_launch(void* const* d_in, const int* in_sizes, int n_in,
                              void* d_out, int out_size) {
    const float* h  = (const float*)d_in[0];
    const float* W  = (const float*)d_in[1];
    const float* ga = (const float*)d_in[2];
    const float* p  = (const float*)d_in[3];
    float* out = (float*)d_out;

    const int R = in_sizes[0] / DIM;          // B*S = 16384

    // host-side polynomial coefficients (doubles; deterministic)
    double Ac[12] = {0}, Bc[12] = {0}, Cc[12] = {0}, Dc[12] = {0};
    Ac[0] = 1.0;
    {
        const double dt = 0.1, beta = 2.0 * sqrt(2.1), c1 = 1.0 - dt * beta;
        for (int n = 0; n < 10; n++) {
            double Cn[12], Dn[12];
            for (int k = 0; k < 12; k++) {
                Cn[k] = c1 * Cc[k] + (k > 0 ? dt * Ac[k - 1] : 0.0);
                Dn[k] = c1 * Dc[k] + (k > 0 ? dt * Bc[k - 1] : 0.0);
            }
            Dn[0] += dt;
            for (int k = 0; k < 12; k++) {
                Cc[k] = Cn[k];  Dc[k] = Dn[k];
                Ac[k] += dt * Cn[k];
                Bc[k] += dt * Dn[k];
            }
        }
    }
    Coef cf;
    for (int j = 0; j < 3; j++)
        for (int m = 0; m < 4; m++) {
            cf.P[j][m] = (float)Ac[4 * j + m];
            cf.Q[j][m] = (float)Bc[4 * j + m];
        }

    const int PAIR_BLKS = (DIM * DIM / 2 + 255) / 256;
    const int HVEC = R * DIM / 4;

    cudaFuncSetAttribute(mma_gemm2, cudaFuncAttributeMaxDynamicSharedMemorySize,
                         2 * MG_BUF);

    build_deg<<<(DIM * 32 + 255) / 256, 256>>>(W);
    build_N<<<PAIR_BLKS, 256>>>(W, p);
    split_h<<<(HVEC + 255) / 256, 256>>>(h, HVEC);

    Job jN2 = {HB_N,  HB_N,  0, 0,      BUF_N2, HB_N2};
    Job jN3 = {HB_N,  HB_N2, 0, 0,      BUF_N3, -1};
    Job jN4 = {HB_N2, HB_N2, 0, 0,      -1,     HB_N4};
    Job jE  = {HB_N4, HB_D2, 1, BUF_D1, -1,     HB_E};
    Job jH  = {HB_N4, HB_E,  2, BUF_D0, -1,     HB_H};

    mma512<<<dim3(8, 8, 1), 256>>>(jN2, jN2, ga);        // N2
    mma512<<<dim3(8, 8, 2), 256>>>(jN3, jN4, ga);        // N3 + N4 (merged)
    build_D<<<PAIR_BLKS, 256>>>(p, cf);
    mma512<<<dim3(8, 8, 1), 256>>>(jE, jE, ga);          // E = N4*D2 + D1
    mma512<<<dim3(8, 8, 1), 256>>>(jH, jH, ga);          // H

    mma_gemm2<<<dim3(R / 128, DIM / 128), 256, 2 * MG_BUF>>>(out);
}

// round 11
// speedup vs baseline: 1.2532x; 1.0024x over previous
#include <cuda_runtime.h>
#include <cuda_bf16.h>
#include <math.h>
#include <cstdint>

// ---------------------------------------------------------------------------
// SOMI settling layer — Paterson-Stockmeyer collapsed formulation.
//   N = |W|/deg - (1.1 + p) on diag;  H = (1-g)I + g*(D0 + N^4(D1 + N^4 D2))
//   out = H @ h over the hidden dim.
// All GEMMs on mma.sync bf16 hi/lo split (hi*hi + hi*lo + lo*hi, fp32 accum),
// cp.async double-buffered pipelines.
//
// HARD RULES LEARNED:
//  R3/R4: never pass __device__ global symbols as host-side kernel args.
//  R6:    harness compiles baseline sm_100 -> no tcgen05/TMEM; mma.sync only.
//  R9:    single-buffered smem mma loops are ~90% stalled -> cp.async pipeline.
// ---------------------------------------------------------------------------

#define DIM 512
#define RMAX (4 * 4096)

// fp32 arena ids
#define BUF_N   0
#define BUF_N2  1
#define BUF_N3  2
#define BUF_D0  3
#define BUF_D1  4
// bf16 hi/lo arena ids
#define HB_N    0
#define HB_N2   1
#define HB_N4   2
#define HB_D2   3
#define HB_E    4
#define HB_H    5

__device__ __align__(16) float g_deg[DIM];
__device__ __align__(16) float g_buf[5][DIM * DIM];
__device__ __align__(16) __nv_bfloat16 g_bhi[6][DIM * DIM];
__device__ __align__(16) __nv_bfloat16 g_blo[6][DIM * DIM];
__device__ __align__(16) __nv_bfloat16 g_hhi[RMAX * DIM];
__device__ __align__(16) __nv_bfloat16 g_hlo[RMAX * DIM];

struct Coef { float P[3][4]; float Q[3][4]; };
struct Job  { int ahl, bhl, mode, addi, outfp, outhl; };

// ======================= helpers ===========================================
__device__ __forceinline__ uint32_t smem_u32(const void* p) {
    uint32_t a;
    asm("{ .reg .u64 t; cvta.to.shared.u64 t, %1; cvt.u32.u64 %0, t; }"
        : "=r"(a) : "l"(p));
    return a;
}
__device__ __forceinline__ uint32_t bf2_pack(__nv_bfloat16 a, __nv_bfloat16 b) {
    __nv_bfloat162 t = __halves2bfloat162(a, b);
    return *reinterpret_cast<uint32_t*>(&t);
}
__device__ __forceinline__ void cp16(uint32_t dst, const void* src) {
    asm volatile("cp.async.cg.shared.global [%0], [%1], 16;"
                 :: "r"(dst), "l"(src) : "memory");
}
#define CP_COMMIT() asm volatile("cp.async.commit_group;" ::: "memory")
#define CP_WAIT1()  asm volatile("cp.async.wait_group 1;" ::: "memory")
#define CP_WAIT0()  asm volatile("cp.async.wait_group 0;" ::: "memory")

__device__ __forceinline__ void ldm_x4(uint32_t& r0, uint32_t& r1,
                                       uint32_t& r2, uint32_t& r3, uint32_t a) {
    asm volatile("ldmatrix.sync.aligned.m8n8.x4.shared.b16 {%0,%1,%2,%3}, [%4];"
                 : "=r"(r0), "=r"(r1), "=r"(r2), "=r"(r3) : "r"(a));
}
__device__ __forceinline__ void ldm_x2(uint32_t& r0, uint32_t& r1, uint32_t a) {
    asm volatile("ldmatrix.sync.aligned.m8n8.x2.shared.b16 {%0,%1}, [%2];"
                 : "=r"(r0), "=r"(r1) : "r"(a));
}
__device__ __forceinline__ void ldm_x2t(uint32_t& r0, uint32_t& r1, uint32_t a) {
    asm volatile("ldmatrix.sync.aligned.m8n8.x2.trans.shared.b16 {%0,%1}, [%2];"
                 : "=r"(r0), "=r"(r1) : "r"(a));
}
__device__ __forceinline__ void mma_bf16(float* c, const uint32_t* a,
                                         const uint32_t* b) {
    asm volatile(
        "mma.sync.aligned.m16n8k16.row.col.f32.bf16.bf16.f32 "
        "{%0,%1,%2,%3}, {%4,%5,%6,%7}, {%8,%9}, {%0,%1,%2,%3};"
        : "+f"(c[0]), "+f"(c[1]), "+f"(c[2]), "+f"(c[3])
        : "r"(a[0]), "r"(a[1]), "r"(a[2]), "r"(a[3]), "r"(b[0]), "r"(b[1]));
}
__device__ __forceinline__ void split_store(int hl, int off, float v0, float v1) {
    __nv_bfloat16 h0 = __float2bfloat16_rn(v0);
    __nv_bfloat16 h1 = __float2bfloat16_rn(v1);
    __nv_bfloat16 l0 = __float2bfloat16_rn(v0 - __bfloat162float(h0));
    __nv_bfloat16 l1 = __float2bfloat16_rn(v1 - __bfloat162float(h1));
    *(uint32_t*)&g_bhi[hl][off] = bf2_pack(h0, h1);
    *(uint32_t*)&g_blo[hl][off] = bf2_pack(l0, l1);
}

// ======================= build kernels =====================================
__global__ void build_deg(const float* __restrict__ W) {
    int warp = (blockIdx.x * blockDim.x + threadIdx.x) >> 5;
    int lane = threadIdx.x & 31;
    if (warp >= DIM) return;
    float s = 0.f;
    const float* row = W + (size_t)warp * DIM;
    for (int d = lane; d < DIM; d += 32) s += fabsf(row[d]);
    #pragma unroll
    for (int o = 16; o > 0; o >>= 1) s += __shfl_down_sync(0xffffffffu, s, o);
    if (lane == 0) g_deg[warp] = fmaxf(s, 1e-8f);
}

__global__ void build_N(const float* __restrict__ W, const float* __restrict__ p) {
    int v = blockIdx.x * blockDim.x + threadIdx.x;
    if (v >= DIM * DIM / 2) return;
    int idx = v * 2;
    int e = idx >> 9;
    int d = idx & (DIM - 1);
    float m0 = fabsf(W[idx]) / g_deg[e];
    float m1 = fabsf(W[idx + 1]) / g_deg[e];
    if (e == d)     m0 -= (1.1f + p[d]);
    if (e == d + 1) m1 -= (1.1f + p[d + 1]);
    g_buf[BUF_N][idx]     = m0;
    g_buf[BUF_N][idx + 1] = m1;
    split_store(HB_N, idx, m0, m1);
}

// h (fp32) -> bf16 hi/lo global buffers (read once by the big GEMM)
__global__ void split_h(const float* __restrict__ h, int nvec) {
    int v = blockIdx.x * blockDim.x + threadIdx.x;   // float4 index
    if (v >= nvec) return;
    float4 x = ((const float4*)h)[v];
    int idx = v * 4;
    __nv_bfloat16 h0 = __float2bfloat16_rn(x.x);
    __nv_bfloat16 h1 = __float2bfloat16_rn(x.y);
    __nv_bfloat16 h2 = __float2bfloat16_rn(x.z);
    __nv_bfloat16 h3 = __float2bfloat16_rn(x.w);
    __nv_bfloat16 l0 = __float2bfloat16_rn(x.x - __bfloat162float(h0));
    __nv_bfloat16 l1 = __float2bfloat16_rn(x.y - __bfloat162float(h1));
    __nv_bfloat16 l2 = __float2bfloat16_rn(x.z - __bfloat162float(h2));
    __nv_bfloat16 l3 = __float2bfloat16_rn(x.w - __bfloat162float(h3));
    *(uint2*)&g_hhi[idx] = make_uint2(bf2_pack(h0, h1), bf2_pack(h2, h3));
    *(uint2*)&g_hlo[idx] = make_uint2(bf2_pack(l0, l1), bf2_pack(l2, l3));
}

__global__ __launch_bounds__(256)
void build_D(const float* __restrict__ p, Coef cf) {
    int v = blockIdx.x * blockDim.x + threadIdx.x;
    if (v >= DIM * DIM / 2) return;
    int idx = v * 2;
    int e = idx >> 9;
    int d = idx & (DIM - 1);
    float r[3][2];
    #pragma unroll
    for (int u = 0; u < 2; u++) {
        int dd = d + u;
        float x0 = (e == dd) ? 1.f : 0.f;
        float x1 = g_buf[BUF_N ][idx + u];
        float x2 = g_buf[BUF_N2][idx + u];
        float x3 = g_buf[BUF_N3][idx + u];
        float pd = p[dd];
        #pragma unroll
        for (int j = 0; j < 3; j++) {
            float vp = cf.P[j][0] * x0 + cf.P[j][1] * x1 + cf.P[j][2] * x2 + cf.P[j][3] * x3;
            float vq = cf.Q[j][0] * x0 + cf.Q[j][1] * x1 + cf.Q[j][2] * x2 + cf.Q[j][3] * x3;
            r[j][u] = vp + vq * pd;
        }
    }
    g_buf[BUF_D0][idx]     = r[0][0];
    g_buf[BUF_D0][idx + 1] = r[0][1];
    g_buf[BUF_D1][idx]     = r[1][0];
    g_buf[BUF_D1][idx + 1] = r[1][1];
    split_store(HB_D2, idx, r[2][0], r[2][1]);
}

// ======================= mma.sync 512^3 GEMM (cp.async pipelined) ==========
// C = A(hi/lo) @ B(hi/lo); CTA 64x64, grid (8,8,z), 8 warps, warp 32x16.
// blockIdx.z selects job j0/j1 (merged independent GEMMs).
// mode 0: plain; 1: += g_buf[addi]; 2: g*(C+g_buf[addi]) + (1-g)I.
#define APAD 40
#define BPAD 72

__global__ __launch_bounds__(256, 1)
void mma512(Job j0, Job j1, const float* __restrict__ ga) {
    __shared__ __align__(16) uint16_t Ahi[2][64][APAD];
    __shared__ __align__(16) uint16_t Alo[2][64][APAD];
    __shared__ __align__(16) uint16_t Bhi[2][32][BPAD];
    __shared__ __align__(16) uint16_t Blo[2][32][BPAD];

    const Job j = (blockIdx.z == 0) ? j0 : j1;
    const int tid  = threadIdx.x;
    const int wid  = tid >> 5;
    const int lane = tid & 31;
    const int wr = wid & 1;
    const int wc = wid >> 1;
    const int brow = blockIdx.x * 64;
    const int bcol = blockIdx.y * 64;

    const __nv_bfloat16* __restrict__ Ah = g_bhi[j.ahl];
    const __nv_bfloat16* __restrict__ Al = g_blo[j.ahl];
    const __nv_bfloat16* __restrict__ Bh = g_bhi[j.bhl];
    const __nv_bfloat16* __restrict__ Bl = g_blo[j.bhl];

    float acc[2][2][4];
    #pragma unroll
    for (int i = 0; i < 2; i++)
        #pragma unroll
        for (int jj = 0; jj < 2; jj++)
            #pragma unroll
            for (int q = 0; q < 4; q++) acc[i][jj][q] = 0.f;

    const int aRow = wr * 32 + (lane & 15);
    const int aKp  = (lane >> 4) * 8;
    const int bLn  = lane & 15;
    const int lar = tid >> 2, laq = tid & 3;   // A: 64 rows x 4 16B-chunks
    const int lbr = tid >> 3, lbq = tid & 7;   // B: 32 rows x 8 16B-chunks

    // prologue: chunk 0 -> buffer 0
    cp16(smem_u32(&Ahi[0][lar][laq * 8]), &Ah[(size_t)(brow + lar) * DIM + laq * 8]);
    cp16(smem_u32(&Alo[0][lar][laq * 8]), &Al[(size_t)(brow + lar) * DIM + laq * 8]);
    cp16(smem_u32(&Bhi[0][lbr][lbq * 8]), &Bh[(size_t)lbr * DIM + bcol + lbq * 8]);
    cp16(smem_u32(&Blo[0][lbr][lbq * 8]), &Bl[(size_t)lbr * DIM + bcol + lbq * 8]);
    CP_COMMIT();

    for (int ch = 0; ch < 16; ch++) {
        if (ch + 1 < 16) {
            const int nb = (ch + 1) & 1;
            const int nk = (ch + 1) * 32;
            cp16(smem_u32(&Ahi[nb][lar][laq * 8]), &Ah[(size_t)(brow + lar) * DIM + nk + laq * 8]);
            cp16(smem_u32(&Alo[nb][lar][laq * 8]), &Al[(size_t)(brow + lar) * DIM + nk + laq * 8]);
            cp16(smem_u32(&Bhi[nb][lbr][lbq * 8]), &Bh[(size_t)(nk + lbr) * DIM + bcol + lbq * 8]);
            cp16(smem_u32(&Blo[nb][lbr][lbq * 8]), &Bl[(size_t)(nk + lbr) * DIM + bcol + lbq * 8]);
            CP_COMMIT();
            CP_WAIT1();
        } else {
            CP_WAIT0();
        }
        __syncthreads();

        const int pb = ch & 1;
        const uint32_t ahB = smem_u32(&Ahi[pb][0][0]);
        const uint32_t alB = smem_u32(&Alo[pb][0][0]);
        const uint32_t bhB = smem_u32(&Bhi[pb][0][0]);
        const uint32_t blB = smem_u32(&Blo[pb][0][0]);

        #pragma unroll
        for (int ks = 0; ks < 2; ks++) {
            const int kk = ks * 16;
            uint32_t ah[2][4], al[2][4], bh[2][2], bl[2][2];
            #pragma unroll
            for (int mt = 0; mt < 2; mt++) {
                uint32_t ao = ((uint32_t)((aRow + mt * 16) * APAD + kk + aKp)) * 2;
                ldm_x4(ah[mt][0], ah[mt][1], ah[mt][2], ah[mt][3], ahB + ao);
                ldm_x4(al[mt][0], al[mt][1], al[mt][2], al[mt][3], alB + ao);
            }
            #pragma unroll
            for (int nt = 0; nt < 2; nt++) {
                uint32_t bo = ((uint32_t)((kk + bLn) * BPAD + wc * 16 + nt * 8)) * 2;
                ldm_x2t(bh[nt][0], bh[nt][1], bhB + bo);
                ldm_x2t(bl[nt][0], bl[nt][1], blB + bo);
            }
            #pragma unroll
            for (int mt = 0; mt < 2; mt++)
                #pragma unroll
                for (int nt = 0; nt < 2; nt++) {
                    mma_bf16(acc[mt][nt], ah[mt], bh[nt]);
                    mma_bf16(acc[mt][nt], ah[mt], bl[nt]);
                    mma_bf16(acc[mt][nt], al[mt], bh[nt]);
                }
        }
        __syncthreads();
    }

    const float g = (j.mode == 2) ? tanhf(ga[0]) : 0.f;
    const float omg = 1.0f - g;
    const int er0 = brow + wr * 32 + (lane >> 2);
    const int ec0 = bcol + wc * 16 + (lane & 3) * 2;

    #pragma unroll
    for (int mt = 0; mt < 2; mt++) {
        #pragma unroll
        for (int nt = 0; nt < 2; nt++) {
            #pragma unroll
            for (int half = 0; half < 2; half++) {
                int r = er0 + mt * 16 + half * 8;
                int c = ec0 + nt * 8;
                int off = r * DIM + c;
                float v0 = acc[mt][nt][half * 2 + 0];
                float v1 = acc[mt][nt][half * 2 + 1];
                if (j.mode == 1) {
                    v0 += g_buf[j.addi][off];
                    v1 += g_buf[j.addi][off + 1];
                } else if (j.mode == 2) {
                    v0 = g * (v0 + g_buf[j.addi][off])     + ((r == c)     ? omg : 0.f);
                    v1 = g * (v1 + g_buf[j.addi][off + 1]) + ((r == c + 1) ? omg : 0.f);
                }
                if (j.outfp >= 0) *(float2*)&g_buf[j.outfp][off] = make_float2(v0, v1);
                if (j.outhl >= 0) split_store(j.outhl, off, v0, v1);
            }
        }
    }
}

// ======================= big GEMM (cp.async pipelined, dyn smem) ===========
// out[r, e] = sum_d h[r, d] * H[e, d]; A from g_hhi/g_hlo, B from HB_H.
// CTA 128x128, grid (R/128, 4), 8 warps (2x4), warp 64x32; BK=32 chunks.
#define MG_BUF  40960
#define MG_AHI  0
#define MG_ALO  10240
#define MG_BHI  20480
#define MG_BLO  30720

__global__ __launch_bounds__(256)
void mma_gemm2(float* __restrict__ out) {
    extern __shared__ char dsm[];
    const uint32_t sb = smem_u32(dsm);

    const int tid  = threadIdx.x;
    const int wid  = tid >> 5;
    const int lane = tid & 31;
    const int wr = wid & 1;
    const int wc = wid >> 1;
    const int brow = blockIdx.x * 128;
    const int bcol = blockIdx.y * 128;

    const __nv_bfloat16* __restrict__ Hh = g_bhi[HB_H];
    const __nv_bfloat16* __restrict__ Hl = g_blo[HB_H];

    float acc[4][4][4];
    #pragma unroll
    for (int i = 0; i < 4; i++)
        #pragma unroll
        for (int jj = 0; jj < 4; jj++)
            #pragma unroll
            for (int q = 0; q < 4; q++) acc[i][jj][q] = 0.f;

    const int aRow = wr * 64 + (lane & 15);
    const int aKp  = (lane >> 4) * 8;
    const int bRow = wc * 32 + (lane & 7);
    const int bKp  = ((lane >> 3) & 1) * 8;
    const int lr0 = tid >> 2, lq0 = tid & 3;   // +64 rows for second iter

    // prologue: chunk 0 -> buffer 0
    #pragma unroll
    for (int i = 0; i < 2; i++) {
        int row = lr0 + i * 64;
        uint32_t d0 = sb + (uint32_t)(row * 80 + lq0 * 16);
        cp16(d0 + MG_AHI, &g_hhi[(size_t)(brow + row) * DIM + lq0 * 8]);
        cp16(d0 + MG_ALO, &g_hlo[(size_t)(brow + row) * DIM + lq0 * 8]);
        cp16(d0 + MG_BHI, &Hh[(size_t)(bcol + row) * DIM + lq0 * 8]);
        cp16(d0 + MG_BLO, &Hl[(size_t)(bcol + row) * DIM + lq0 * 8]);
    }
    CP_COMMIT();

    for (int ch = 0; ch < 16; ch++) {
        if (ch + 1 < 16) {
            const int nb = (ch + 1) & 1;
            const int nk = (ch + 1) * 32;
            #pragma unroll
            for (int i = 0; i < 2; i++) {
                int row = lr0 + i * 64;
                uint32_t d0 = sb + (uint32_t)(nb * MG_BUF + row * 80 + lq0 * 16);
                cp16(d0 + MG_AHI, &g_hhi[(size_t)(brow + row) * DIM + nk + lq0 * 8]);
                cp16(d0 + MG_ALO, &g_hlo[(size_t)(brow + row) * DIM + nk + lq0 * 8]);
                cp16(d0 + MG_BHI, &Hh[(size_t)(bcol + row) * DIM + nk + lq0 * 8]);
                cp16(d0 + MG_BLO, &Hl[(size_t)(bcol + row) * DIM + nk + lq0 * 8]);
            }
            CP_COMMIT();
            CP_WAIT1();
        } else {
            CP_WAIT0();
        }
        __syncthreads();

        const uint32_t bufb = sb + (uint32_t)((ch & 1) * MG_BUF);
        #pragma unroll
        for (int ks = 0; ks < 2; ks++) {
            const int kk = ks * 16;
            uint32_t ah[4][4], al[4][4], bh[4][2], bl[4][2];
            #pragma unroll
            for (int mt = 0; mt < 4; mt++) {
                uint32_t ao = ((uint32_t)((aRow + mt * 16) * APAD + kk + aKp)) * 2;
                ldm_x4(ah[mt][0], ah[mt][1], ah[mt][2], ah[mt][3], bufb + MG_AHI + ao);
                ldm_x4(al[mt][0], al[mt][1], al[mt][2], al[mt][3], bufb + MG_ALO + ao);
            }
            #pragma unroll
            for (int nt = 0; nt < 4; nt++) {
                uint32_t bo = ((uint32_t)((bRow + nt * 8) * APAD + kk + bKp)) * 2;
                ldm_x2(bh[nt][0], bh[nt][1], bufb + MG_BHI + bo);
                ldm_x2(bl[nt][0], bl[nt][1], bufb + MG_BLO + bo);
            }
            #pragma unroll
            for (int mt = 0; mt < 4; mt++)
                #pragma unroll
                for (int nt = 0; nt < 4; nt++) {
                    mma_bf16(acc[mt][nt], ah[mt], bh[nt]);
                    mma_bf16(acc[mt][nt], ah[mt], bl[nt]);
                    mma_bf16(acc[mt][nt], al[mt], bh[nt]);
                }
        }
        __syncthreads();
    }

    const int er = brow + wr * 64 + (lane >> 2);
    const int ec = bcol + wc * 32 + (lane & 3) * 2;
    #pragma unroll
    for (int mt = 0; mt < 4; mt++) {
        #pragma unroll
        for (int nt = 0; nt < 4; nt++) {
            float* p0 = out + (size_t)(er + mt * 16) * DIM + ec + nt * 8;
            *(float2*)p0 = make_float2(acc[mt][nt][0], acc[mt][nt][1]);
            float* p1 = out + (size_t)(er + mt * 16 + 8) * DIM + ec + nt * 8;
            *(float2*)p1 = make_float2(acc[mt][nt][2], acc[mt][nt][3]);
        }
    }
}

// ---------------------------------------------------------------------------
extern "C" void kernel_launch(void* const* d_in, const int* in_sizes, int n_in,
                              void* d_out, int out_size) {
    const float* h  = (const float*)d_in[0];
    const float* W  = (const float*)d_in[1];
    const float* ga = (const float*)d_in[2];
    const float* p  = (const float*)d_in[3];
    float* out = (float*)d_out;

    const int R = in_sizes[0] / DIM;          // B*S = 16384

    // host-side polynomial coefficients (doubles; deterministic)
    double Ac[12] = {0}, Bc[12] = {0}, Cc[12] = {0}, Dc[12] = {0};
    Ac[0] = 1.0;
    {
        const double dt = 0.1, beta = 2.0 * sqrt(2.1), c1 = 1.0 - dt * beta;
        for (int n = 0; n < 10; n++) {
            double Cn[12], Dn[12];
            for (int k = 0; k < 12; k++) {
                Cn[k] = c1 * Cc[k] + (k > 0 ? dt * Ac[k - 1] : 0.0);
                Dn[k] = c1 * Dc[k] + (k > 0 ? dt * Bc[k - 1] : 0.0);
            }
            Dn[0] += dt;
            for (int k = 0; k < 12; k++) {
                Cc[k] = Cn[k];  Dc[k] = Dn[k];
                Ac[k] += dt * Cn[k];
                Bc[k] += dt * Dn[k];
            }
        }
    }
    Coef cf;
    for (int j = 0; j < 3; j++)
        for (int m = 0; m < 4; m++) {
            cf.P[j][m] = (float)Ac[4 * j + m];
            cf.Q[j][m] = (float)Bc[4 * j + m];
        }

    const int PAIR_BLKS = (DIM * DIM / 2 + 255) / 256;
    const int HVEC = R * DIM / 4;

    cudaFuncSetAttribute(mma_gemm2, cudaFuncAttributeMaxDynamicSharedMemorySize,
                         2 * MG_BUF);

    build_deg<<<(DIM * 32 + 255) / 256, 256>>>(W);
    build_N<<<PAIR_BLKS, 256>>>(W, p);
    split_h<<<(HVEC + 255) / 256, 256>>>(h, HVEC);

    Job jN2 = {HB_N,  HB_N,  0, 0,      BUF_N2, HB_N2};
    Job jN3 = {HB_N,  HB_N2, 0, 0,      BUF_N3, -1};
    Job jN4 = {HB_N2, HB_N2, 0, 0,      -1,     HB_N4};
    Job jE  = {HB_N4, HB_D2, 1, BUF_D1, -1,     HB_E};
    Job jH  = {HB_N4, HB_E,  2, BUF_D0, -1,     HB_H};

    mma512<<<dim3(8, 8, 1), 256>>>(jN2, jN2, ga);        // N2
    mma512<<<dim3(8, 8, 2), 256>>>(jN3, jN4, ga);        // N3 + N4 (merged)
    build_D<<<PAIR_BLKS, 256>>>(p, cf);
    mma512<<<dim3(8, 8, 1), 256>>>(jE, jE, ga);          // E = N4*D2 + D1
    mma512<<<dim3(8, 8, 1), 256>>>(jH, jH, ga);          // H

    mma_gemm2<<<dim3(R / 128, DIM / 128), 256, 2 * MG_BUF>>>(out);
}

// round 12
// speedup vs baseline: 1.8571x; 1.4819x over previous
#include <cuda_runtime.h>
#include <cuda_bf16.h>
#include <cuda_fp16.h>
#include <math.h>
#include <cstdint>

// ---------------------------------------------------------------------------
// SOMI settling layer — Paterson-Stockmeyer collapsed formulation.
//   N = |W|/deg - (1.1 + p) on diag;  H = (1-g)I + g*(D0 + N^4(D1 + N^4 D2))
//   out = H @ h over the hidden dim.
// Poly chain: mma.sync bf16 hi/lo 3-product (rel err ~4e-6).
// Big GEMM: mma.sync fp16 single-product (rel err ~2e-4; 3x less MMA work —
// the 3-product version was AT the legacy-HMMA compute floor).
//
// HARD RULES LEARNED:
//  R3/R4: never pass __device__ global symbols as host-side kernel args.
//  R6:    harness compiles baseline sm_100 -> no tcgen05/TMEM; mma.sync only.
//  R9:    single-buffered smem mma loops are ~90% stalled -> cp.async pipeline.
//  R11:   big GEMM hit the mma.sync compute floor -> reduce MMA work (fp16).
// ---------------------------------------------------------------------------

#define DIM 512
#define RMAX (4 * 4096)

// fp32 arena ids
#define BUF_N   0
#define BUF_N2  1
#define BUF_N3  2
#define BUF_D0  3
#define BUF_D1  4
// bf16 hi/lo arena ids
#define HB_N    0
#define HB_N2   1
#define HB_N4   2
#define HB_D2   3
#define HB_E    4

__device__ __align__(16) float g_deg[DIM];
__device__ __align__(16) float g_buf[5][DIM * DIM];
__device__ __align__(16) __nv_bfloat16 g_bhi[5][DIM * DIM];
__device__ __align__(16) __nv_bfloat16 g_blo[5][DIM * DIM];
__device__ __align__(16) __half g_Hf[DIM * DIM];      // H in fp16 (big GEMM B)
__device__ __align__(16) __half g_hf[RMAX * DIM];     // h in fp16 (big GEMM A)

struct Coef { float P[3][4]; float Q[3][4]; };
struct Job  { int ahl, bhl, mode, addi, outfp, outhl, outf16; };

// ======================= helpers ===========================================
__device__ __forceinline__ uint32_t smem_u32(const void* p) {
    uint32_t a;
    asm("{ .reg .u64 t; cvta.to.shared.u64 t, %1; cvt.u32.u64 %0, t; }"
        : "=r"(a) : "l"(p));
    return a;
}
__device__ __forceinline__ uint32_t bf2_pack(__nv_bfloat16 a, __nv_bfloat16 b) {
    __nv_bfloat162 t = __halves2bfloat162(a, b);
    return *reinterpret_cast<uint32_t*>(&t);
}
__device__ __forceinline__ void cp16(uint32_t dst, const void* src) {
    asm volatile("cp.async.cg.shared.global [%0], [%1], 16;"
                 :: "r"(dst), "l"(src) : "memory");
}
#define CP_COMMIT() asm volatile("cp.async.commit_group;" ::: "memory")
#define CP_WAIT1()  asm volatile("cp.async.wait_group 1;" ::: "memory")
#define CP_WAIT0()  asm volatile("cp.async.wait_group 0;" ::: "memory")

__device__ __forceinline__ void ldm_x4(uint32_t& r0, uint32_t& r1,
                                       uint32_t& r2, uint32_t& r3, uint32_t a) {
    asm volatile("ldmatrix.sync.aligned.m8n8.x4.shared.b16 {%0,%1,%2,%3}, [%4];"
                 : "=r"(r0), "=r"(r1), "=r"(r2), "=r"(r3) : "r"(a));
}
__device__ __forceinline__ void ldm_x2(uint32_t& r0, uint32_t& r1, uint32_t a) {
    asm volatile("ldmatrix.sync.aligned.m8n8.x2.shared.b16 {%0,%1}, [%2];"
                 : "=r"(r0), "=r"(r1) : "r"(a));
}
__device__ __forceinline__ void ldm_x2t(uint32_t& r0, uint32_t& r1, uint32_t a) {
    asm volatile("ldmatrix.sync.aligned.m8n8.x2.trans.shared.b16 {%0,%1}, [%2];"
                 : "=r"(r0), "=r"(r1) : "r"(a));
}
__device__ __forceinline__ void mma_bf16(float* c, const uint32_t* a,
                                         const uint32_t* b) {
    asm volatile(
        "mma.sync.aligned.m16n8k16.row.col.f32.bf16.bf16.f32 "
        "{%0,%1,%2,%3}, {%4,%5,%6,%7}, {%8,%9}, {%0,%1,%2,%3};"
        : "+f"(c[0]), "+f"(c[1]), "+f"(c[2]), "+f"(c[3])
        : "r"(a[0]), "r"(a[1]), "r"(a[2]), "r"(a[3]), "r"(b[0]), "r"(b[1]));
}
__device__ __forceinline__ void mma_f16(float* c, const uint32_t* a,
                                        const uint32_t* b) {
    asm volatile(
        "mma.sync.aligned.m16n8k16.row.col.f32.f16.f16.f32 "
        "{%0,%1,%2,%3}, {%4,%5,%6,%7}, {%8,%9}, {%0,%1,%2,%3};"
        : "+f"(c[0]), "+f"(c[1]), "+f"(c[2]), "+f"(c[3])
        : "r"(a[0]), "r"(a[1]), "r"(a[2]), "r"(a[3]), "r"(b[0]), "r"(b[1]));
}
__device__ __forceinline__ void split_store(int hl, int off, float v0, float v1) {
    __nv_bfloat16 h0 = __float2bfloat16_rn(v0);
    __nv_bfloat16 h1 = __float2bfloat16_rn(v1);
    __nv_bfloat16 l0 = __float2bfloat16_rn(v0 - __bfloat162float(h0));
    __nv_bfloat16 l1 = __float2bfloat16_rn(v1 - __bfloat162float(h1));
    *(uint32_t*)&g_bhi[hl][off] = bf2_pack(h0, h1);
    *(uint32_t*)&g_blo[hl][off] = bf2_pack(l0, l1);
}

// ======================= build kernels =====================================
__global__ void build_deg(const float* __restrict__ W) {
    int warp = (blockIdx.x * blockDim.x + threadIdx.x) >> 5;
    int lane = threadIdx.x & 31;
    if (warp >= DIM) return;
    float s = 0.f;
    const float* row = W + (size_t)warp * DIM;
    for (int d = lane; d < DIM; d += 32) s += fabsf(row[d]);
    #pragma unroll
    for (int o = 16; o > 0; o >>= 1) s += __shfl_down_sync(0xffffffffu, s, o);
    if (lane == 0) g_deg[warp] = fmaxf(s, 1e-8f);
}

__global__ void build_N(const float* __restrict__ W, const float* __restrict__ p) {
    int v = blockIdx.x * blockDim.x + threadIdx.x;
    if (v >= DIM * DIM / 2) return;
    int idx = v * 2;
    int e = idx >> 9;
    int d = idx & (DIM - 1);
    float m0 = fabsf(W[idx]) / g_deg[e];
    float m1 = fabsf(W[idx + 1]) / g_deg[e];
    if (e == d)     m0 -= (1.1f + p[d]);
    if (e == d + 1) m1 -= (1.1f + p[d + 1]);
    g_buf[BUF_N][idx]     = m0;
    g_buf[BUF_N][idx + 1] = m1;
    split_store(HB_N, idx, m0, m1);
}

// h (fp32) -> fp16 (read by the big GEMM)
__global__ void split_h(const float* __restrict__ h, int nvec) {
    int v = blockIdx.x * blockDim.x + threadIdx.x;   // float4 index
    if (v >= nvec) return;
    float4 x = ((const float4*)h)[v];
    int idx = v * 4;
    __half2 a = __floats2half2_rn(x.x, x.y);
    __half2 b = __floats2half2_rn(x.z, x.w);
    *(uint2*)&g_hf[idx] = make_uint2(*(uint32_t*)&a, *(uint32_t*)&b);
}

__global__ __launch_bounds__(256)
void build_D(const float* __restrict__ p, Coef cf) {
    int v = blockIdx.x * blockDim.x + threadIdx.x;
    if (v >= DIM * DIM / 2) return;
    int idx = v * 2;
    int e = idx >> 9;
    int d = idx & (DIM - 1);
    float r[3][2];
    #pragma unroll
    for (int u = 0; u < 2; u++) {
        int dd = d + u;
        float x0 = (e == dd) ? 1.f : 0.f;
        float x1 = g_buf[BUF_N ][idx + u];
        float x2 = g_buf[BUF_N2][idx + u];
        float x3 = g_buf[BUF_N3][idx + u];
        float pd = p[dd];
        #pragma unroll
        for (int j = 0; j < 3; j++) {
            float vp = cf.P[j][0] * x0 + cf.P[j][1] * x1 + cf.P[j][2] * x2 + cf.P[j][3] * x3;
            float vq = cf.Q[j][0] * x0 + cf.Q[j][1] * x1 + cf.Q[j][2] * x2 + cf.Q[j][3] * x3;
            r[j][u] = vp + vq * pd;
        }
    }
    g_buf[BUF_D0][idx]     = r[0][0];
    g_buf[BUF_D0][idx + 1] = r[0][1];
    g_buf[BUF_D1][idx]     = r[1][0];
    g_buf[BUF_D1][idx + 1] = r[1][1];
    split_store(HB_D2, idx, r[2][0], r[2][1]);
}

// ======================= mma.sync 512^3 GEMM (cp.async pipelined) ==========
// C = A(hi/lo) @ B(hi/lo); CTA 64x64, grid (8,8,z), 8 warps, warp 32x16.
// mode 0: plain; 1: += g_buf[addi]; 2: g*(C+g_buf[addi]) + (1-g)I.
// outf16: also write fp16 H matrix for the big GEMM.
#define APAD 40
#define BPAD 72

__global__ __launch_bounds__(256, 1)
void mma512(Job j0, Job j1, const float* __restrict__ ga) {
    __shared__ __align__(16) uint16_t Ahi[2][64][APAD];
    __shared__ __align__(16) uint16_t Alo[2][64][APAD];
    __shared__ __align__(16) uint16_t Bhi[2][32][BPAD];
    __shared__ __align__(16) uint16_t Blo[2][32][BPAD];

    const Job j = (blockIdx.z == 0) ? j0 : j1;
    const int tid  = threadIdx.x;
    const int wid  = tid >> 5;
    const int lane = tid & 31;
    const int wr = wid & 1;
    const int wc = wid >> 1;
    const int brow = blockIdx.x * 64;
    const int bcol = blockIdx.y * 64;

    const __nv_bfloat16* __restrict__ Ah = g_bhi[j.ahl];
    const __nv_bfloat16* __restrict__ Al = g_blo[j.ahl];
    const __nv_bfloat16* __restrict__ Bh = g_bhi[j.bhl];
    const __nv_bfloat16* __restrict__ Bl = g_blo[j.bhl];

    float acc[2][2][4];
    #pragma unroll
    for (int i = 0; i < 2; i++)
        #pragma unroll
        for (int jj = 0; jj < 2; jj++)
            #pragma unroll
            for (int q = 0; q < 4; q++) acc[i][jj][q] = 0.f;

    const int aRow = wr * 32 + (lane & 15);
    const int aKp  = (lane >> 4) * 8;
    const int bLn  = lane & 15;
    const int lar = tid >> 2, laq = tid & 3;
    const int lbr = tid >> 3, lbq = tid & 7;

    cp16(smem_u32(&Ahi[0][lar][laq * 8]), &Ah[(size_t)(brow + lar) * DIM + laq * 8]);
    cp16(smem_u32(&Alo[0][lar][laq * 8]), &Al[(size_t)(brow + lar) * DIM + laq * 8]);
    cp16(smem_u32(&Bhi[0][lbr][lbq * 8]), &Bh[(size_t)lbr * DIM + bcol + lbq * 8]);
    cp16(smem_u32(&Blo[0][lbr][lbq * 8]), &Bl[(size_t)lbr * DIM + bcol + lbq * 8]);
    CP_COMMIT();

    for (int ch = 0; ch < 16; ch++) {
        if (ch + 1 < 16) {
            const int nb = (ch + 1) & 1;
            const int nk = (ch + 1) * 32;
            cp16(smem_u32(&Ahi[nb][lar][laq * 8]), &Ah[(size_t)(brow + lar) * DIM + nk + laq * 8]);
            cp16(smem_u32(&Alo[nb][lar][laq * 8]), &Al[(size_t)(brow + lar) * DIM + nk + laq * 8]);
            cp16(smem_u32(&Bhi[nb][lbr][lbq * 8]), &Bh[(size_t)(nk + lbr) * DIM + bcol + lbq * 8]);
            cp16(smem_u32(&Blo[nb][lbr][lbq * 8]), &Bl[(size_t)(nk + lbr) * DIM + bcol + lbq * 8]);
            CP_COMMIT();
            CP_WAIT1();
        } else {
            CP_WAIT0();
        }
        __syncthreads();

        const int pb = ch & 1;
        const uint32_t ahB = smem_u32(&Ahi[pb][0][0]);
        const uint32_t alB = smem_u32(&Alo[pb][0][0]);
        const uint32_t bhB = smem_u32(&Bhi[pb][0][0]);
        const uint32_t blB = smem_u32(&Blo[pb][0][0]);

        #pragma unroll
        for (int ks = 0; ks < 2; ks++) {
            const int kk = ks * 16;
            uint32_t ah[2][4], al[2][4], bh[2][2], bl[2][2];
            #pragma unroll
            for (int mt = 0; mt < 2; mt++) {
                uint32_t ao = ((uint32_t)((aRow + mt * 16) * APAD + kk + aKp)) * 2;
                ldm_x4(ah[mt][0], ah[mt][1], ah[mt][2], ah[mt][3], ahB + ao);
                ldm_x4(al[mt][0], al[mt][1], al[mt][2], al[mt][3], alB + ao);
            }
            #pragma unroll
            for (int nt = 0; nt < 2; nt++) {
                uint32_t bo = ((uint32_t)((kk + bLn) * BPAD + wc * 16 + nt * 8)) * 2;
                ldm_x2t(bh[nt][0], bh[nt][1], bhB + bo);
                ldm_x2t(bl[nt][0], bl[nt][1], blB + bo);
            }
            #pragma unroll
            for (int mt = 0; mt < 2; mt++)
                #pragma unroll
                for (int nt = 0; nt < 2; nt++) {
                    mma_bf16(acc[mt][nt], ah[mt], bh[nt]);
                    mma_bf16(acc[mt][nt], ah[mt], bl[nt]);
                    mma_bf16(acc[mt][nt], al[mt], bh[nt]);
                }
        }
        __syncthreads();
    }

    const float g = (j.mode == 2) ? tanhf(ga[0]) : 0.f;
    const float omg = 1.0f - g;
    const int er0 = brow + wr * 32 + (lane >> 2);
    const int ec0 = bcol + wc * 16 + (lane & 3) * 2;

    #pragma unroll
    for (int mt = 0; mt < 2; mt++) {
        #pragma unroll
        for (int nt = 0; nt < 2; nt++) {
            #pragma unroll
            for (int half = 0; half < 2; half++) {
                int r = er0 + mt * 16 + half * 8;
                int c = ec0 + nt * 8;
                int off = r * DIM + c;
                float v0 = acc[mt][nt][half * 2 + 0];
                float v1 = acc[mt][nt][half * 2 + 1];
                if (j.mode == 1) {
                    v0 += g_buf[j.addi][off];
                    v1 += g_buf[j.addi][off + 1];
                } else if (j.mode == 2) {
                    v0 = g * (v0 + g_buf[j.addi][off])     + ((r == c)     ? omg : 0.f);
                    v1 = g * (v1 + g_buf[j.addi][off + 1]) + ((r == c + 1) ? omg : 0.f);
                }
                if (j.outfp >= 0) *(float2*)&g_buf[j.outfp][off] = make_float2(v0, v1);
                if (j.outhl >= 0) split_store(j.outhl, off, v0, v1);
                if (j.outf16) {
                    __half2 hv = __floats2half2_rn(v0, v1);
                    *(uint32_t*)&g_Hf[off] = *(uint32_t*)&hv;
                }
            }
        }
    }
}

// ======================= big GEMM: fp16 single-product =====================
// out[r, e] = sum_d h[r, d] * H[e, d]; A = g_hf, B = g_Hf (both fp16).
// CTA 128x128, grid (R/128, 4), 8 warps (2x4), warp 64x32; BK=32 chunks,
// cp.async double-buffered. Static smem 40KB.
__global__ __launch_bounds__(256)
void mma_gemm3(float* __restrict__ out) {
    __shared__ __align__(16) uint16_t As[2][128][APAD];
    __shared__ __align__(16) uint16_t Bs[2][128][APAD];

    const int tid  = threadIdx.x;
    const int wid  = tid >> 5;
    const int lane = tid & 31;
    const int wr = wid & 1;
    const int wc = wid >> 1;
    const int brow = blockIdx.x * 128;
    const int bcol = blockIdx.y * 128;

    float acc[4][4][4];
    #pragma unroll
    for (int i = 0; i < 4; i++)
        #pragma unroll
        for (int jj = 0; jj < 4; jj++)
            #pragma unroll
            for (int q = 0; q < 4; q++) acc[i][jj][q] = 0.f;

    const int aRow = wr * 64 + (lane & 15);
    const int aKp  = (lane >> 4) * 8;
    const int bRow = wc * 32 + (lane & 7);
    const int bKp  = ((lane >> 3) & 1) * 8;
    const int lr0 = tid >> 2, lq0 = tid & 3;   // 64 rows per pass, 4x16B per row

    // prologue: chunk 0 -> buffer 0
    #pragma unroll
    for (int i = 0; i < 2; i++) {
        int row = lr0 + i * 64;
        cp16(smem_u32(&As[0][row][lq0 * 8]), &g_hf[(size_t)(brow + row) * DIM + lq0 * 8]);
        cp16(smem_u32(&Bs[0][row][lq0 * 8]), &g_Hf[(size_t)(bcol + row) * DIM + lq0 * 8]);
    }
    CP_COMMIT();

    for (int ch = 0; ch < 16; ch++) {
        if (ch + 1 < 16) {
            const int nb = (ch + 1) & 1;
            const int nk = (ch + 1) * 32;
            #pragma unroll
            for (int i = 0; i < 2; i++) {
                int row = lr0 + i * 64;
                cp16(smem_u32(&As[nb][row][lq0 * 8]), &g_hf[(size_t)(brow + row) * DIM + nk + lq0 * 8]);
                cp16(smem_u32(&Bs[nb][row][lq0 * 8]), &g_Hf[(size_t)(bcol + row) * DIM + nk + lq0 * 8]);
            }
            CP_COMMIT();
            CP_WAIT1();
        } else {
            CP_WAIT0();
        }
        __syncthreads();

        const int pb = ch & 1;
        const uint32_t aB = smem_u32(&As[pb][0][0]);
        const uint32_t bB = smem_u32(&Bs[pb][0][0]);

        #pragma unroll
        for (int ks = 0; ks < 2; ks++) {
            const int kk = ks * 16;
            uint32_t af[4][4], bf[4][2];
            #pragma unroll
            for (int mt = 0; mt < 4; mt++) {
                uint32_t ao = ((uint32_t)((aRow + mt * 16) * APAD + kk + aKp)) * 2;
                ldm_x4(af[mt][0], af[mt][1], af[mt][2], af[mt][3], aB + ao);
            }
            #pragma unroll
            for (int nt = 0; nt < 4; nt++) {
                uint32_t bo = ((uint32_t)((bRow + nt * 8) * APAD + kk + bKp)) * 2;
                ldm_x2(bf[nt][0], bf[nt][1], bB + bo);
            }
            #pragma unroll
            for (int mt = 0; mt < 4; mt++)
                #pragma unroll
                for (int nt = 0; nt < 4; nt++)
                    mma_f16(acc[mt][nt], af[mt], bf[nt]);
        }
        __syncthreads();
    }

    const int er = brow + wr * 64 + (lane >> 2);
    const int ec = bcol + wc * 32 + (lane & 3) * 2;
    #pragma unroll
    for (int mt = 0; mt < 4; mt++) {
        #pragma unroll
        for (int nt = 0; nt < 4; nt++) {
            float* p0 = out + (size_t)(er + mt * 16) * DIM + ec + nt * 8;
            *(float2*)p0 = make_float2(acc[mt][nt][0], acc[mt][nt][1]);
            float* p1 = out + (size_t)(er + mt * 16 + 8) * DIM + ec + nt * 8;
            *(float2*)p1 = make_float2(acc[mt][nt][2], acc[mt][nt][3]);
        }
    }
}

// ---------------------------------------------------------------------------
extern "C" void kernel_launch(void* const* d_in, const int* in_sizes, int n_in,
                              void* d_out, int out_size) {
    const float* h  = (const float*)d_in[0];
    const float* W  = (const float*)d_in[1];
    const float* ga = (const float*)d_in[2];
    const float* p  = (const float*)d_in[3];
    float* out = (float*)d_out;

    const int R = in_sizes[0] / DIM;          // B*S = 16384

    // host-side polynomial coefficients (doubles; deterministic)
    double Ac[12] = {0}, Bc[12] = {0}, Cc[12] = {0}, Dc[12] = {0};
    Ac[0] = 1.0;
    {
        const double dt = 0.1, beta = 2.0 * sqrt(2.1), c1 = 1.0 - dt * beta;
        for (int n = 0; n < 10; n++) {
            double Cn[12], Dn[12];
            for (int k = 0; k < 12; k++) {
                Cn[k] = c1 * Cc[k] + (k > 0 ? dt * Ac[k - 1] : 0.0);
                Dn[k] = c1 * Dc[k] + (k > 0 ? dt * Bc[k - 1] : 0.0);
            }
            Dn[0] += dt;
            for (int k = 0; k < 12; k++) {
                Cc[k] = Cn[k];  Dc[k] = Dn[k];
                Ac[k] += dt * Cn[k];
                Bc[k] += dt * Dn[k];
            }
        }
    }
    Coef cf;
    for (int j = 0; j < 3; j++)
        for (int m = 0; m < 4; m++) {
            cf.P[j][m] = (float)Ac[4 * j + m];
            cf.Q[j][m] = (float)Bc[4 * j + m];
        }

    const int PAIR_BLKS = (DIM * DIM / 2 + 255) / 256;
    const int HVEC = R * DIM / 4;

    build_deg<<<(DIM * 32 + 255) / 256, 256>>>(W);
    build_N<<<PAIR_BLKS, 256>>>(W, p);
    split_h<<<(HVEC + 255) / 256, 256>>>(h, HVEC);

    Job jN2 = {HB_N,  HB_N,  0, 0,      BUF_N2, HB_N2, 0};
    Job jN3 = {HB_N,  HB_N2, 0, 0,      BUF_N3, -1,    0};
    Job jN4 = {HB_N2, HB_N2, 0, 0,      -1,     HB_N4, 0};
    Job jE  = {HB_N4, HB_D2, 1, BUF_D1, -1,     HB_E,  0};
    Job jH  = {HB_N4, HB_E,  2, BUF_D0, -1,     -1,    1};

    mma512<<<dim3(8, 8, 1), 256>>>(jN2, jN2, ga);        // N2
    mma512<<<dim3(8, 8, 2), 256>>>(jN3, jN4, ga);        // N3 + N4 (merged)
    build_D<<<PAIR_BLKS, 256>>>(p, cf);
    mma512<<<dim3(8, 8, 1), 256>>>(jE, jE, ga);          // E = N4*D2 + D1
    mma512<<<dim3(8, 8, 1), 256>>>(jH, jH, ga);          // H (emits fp16)

    mma_gemm3<<<dim3(R / 128, DIM / 128), 256>>>(out);
}

// round 13
// speedup vs baseline: 2.0392x; 1.0980x over previous
#include <cuda_runtime.h>
#include <cuda_bf16.h>
#include <cuda_fp16.h>
#include <math.h>
#include <cstdint>

// ---------------------------------------------------------------------------
// SOMI settling layer — Paterson-Stockmeyer collapsed formulation.
//   N = |W|/deg - (1.1 + p) on diag;  H = (1-g)I + g*(D0 + N^4(D1 + N^4 D2))
//   out = H @ h over the hidden dim.
// Poly chain: mma.sync bf16 hi/lo 3-product (rel err ~4e-6), 32x64 CTA tiles
// (128 CTAs — R12's 64-CTA version left 57% of SMs idle).
// Big GEMM: mma.sync fp16 single-product (rel err ~3e-4).
//
// HARD RULES LEARNED:
//  R3/R4: never pass __device__ global symbols as host-side kernel args.
//  R6:    harness compiles baseline sm_100 -> no tcgen05/TMEM; mma.sync only.
//  R9:    single-buffered smem mma loops are ~90% stalled -> cp.async pipeline.
//  R11:   big GEMM hit the mma.sync compute floor -> fp16 single product.
// ---------------------------------------------------------------------------

#define DIM 512
#define RMAX (4 * 4096)

// fp32 arena ids
#define BUF_N   0
#define BUF_N2  1
#define BUF_N3  2
#define BUF_D0  3
#define BUF_D1  4
// bf16 hi/lo arena ids
#define HB_N    0
#define HB_N2   1
#define HB_N4   2
#define HB_D2   3
#define HB_E    4

__device__ __align__(16) float g_deg[DIM];
__device__ __align__(16) float g_buf[5][DIM * DIM];
__device__ __align__(16) __nv_bfloat16 g_bhi[5][DIM * DIM];
__device__ __align__(16) __nv_bfloat16 g_blo[5][DIM * DIM];
__device__ __align__(16) __half g_Hf[DIM * DIM];      // H in fp16 (big GEMM B)
__device__ __align__(16) __half g_hf[RMAX * DIM];     // h in fp16 (big GEMM A)

struct Coef { float P[3][4]; float Q[3][4]; };
struct Job  { int ahl, bhl, mode, addi, outfp, outhl, outf16; };

// ======================= helpers ===========================================
__device__ __forceinline__ uint32_t smem_u32(const void* p) {
    uint32_t a;
    asm("{ .reg .u64 t; cvta.to.shared.u64 t, %1; cvt.u32.u64 %0, t; }"
        : "=r"(a) : "l"(p));
    return a;
}
__device__ __forceinline__ uint32_t bf2_pack(__nv_bfloat16 a, __nv_bfloat16 b) {
    __nv_bfloat162 t = __halves2bfloat162(a, b);
    return *reinterpret_cast<uint32_t*>(&t);
}
__device__ __forceinline__ void cp16(uint32_t dst, const void* src) {
    asm volatile("cp.async.cg.shared.global [%0], [%1], 16;"
                 :: "r"(dst), "l"(src) : "memory");
}
#define CP_COMMIT() asm volatile("cp.async.commit_group;" ::: "memory")
#define CP_WAIT1()  asm volatile("cp.async.wait_group 1;" ::: "memory")
#define CP_WAIT0()  asm volatile("cp.async.wait_group 0;" ::: "memory")

__device__ __forceinline__ void ldm_x4(uint32_t& r0, uint32_t& r1,
                                       uint32_t& r2, uint32_t& r3, uint32_t a) {
    asm volatile("ldmatrix.sync.aligned.m8n8.x4.shared.b16 {%0,%1,%2,%3}, [%4];"
                 : "=r"(r0), "=r"(r1), "=r"(r2), "=r"(r3) : "r"(a));
}
__device__ __forceinline__ void ldm_x2(uint32_t& r0, uint32_t& r1, uint32_t a) {
    asm volatile("ldmatrix.sync.aligned.m8n8.x2.shared.b16 {%0,%1}, [%2];"
                 : "=r"(r0), "=r"(r1) : "r"(a));
}
__device__ __forceinline__ void ldm_x2t(uint32_t& r0, uint32_t& r1, uint32_t a) {
    asm volatile("ldmatrix.sync.aligned.m8n8.x2.trans.shared.b16 {%0,%1}, [%2];"
                 : "=r"(r0), "=r"(r1) : "r"(a));
}
__device__ __forceinline__ void mma_bf16(float* c, const uint32_t* a,
                                         const uint32_t* b) {
    asm volatile(
        "mma.sync.aligned.m16n8k16.row.col.f32.bf16.bf16.f32 "
        "{%0,%1,%2,%3}, {%4,%5,%6,%7}, {%8,%9}, {%0,%1,%2,%3};"
        : "+f"(c[0]), "+f"(c[1]), "+f"(c[2]), "+f"(c[3])
        : "r"(a[0]), "r"(a[1]), "r"(a[2]), "r"(a[3]), "r"(b[0]), "r"(b[1]));
}
__device__ __forceinline__ void mma_f16(float* c, const uint32_t* a,
                                        const uint32_t* b) {
    asm volatile(
        "mma.sync.aligned.m16n8k16.row.col.f32.f16.f16.f32 "
        "{%0,%1,%2,%3}, {%4,%5,%6,%7}, {%8,%9}, {%0,%1,%2,%3};"
        : "+f"(c[0]), "+f"(c[1]), "+f"(c[2]), "+f"(c[3])
        : "r"(a[0]), "r"(a[1]), "r"(a[2]), "r"(a[3]), "r"(b[0]), "r"(b[1]));
}
__device__ __forceinline__ void split_store(int hl, int off, float v0, float v1) {
    __nv_bfloat16 h0 = __float2bfloat16_rn(v0);
    __nv_bfloat16 h1 = __float2bfloat16_rn(v1);
    __nv_bfloat16 l0 = __float2bfloat16_rn(v0 - __bfloat162float(h0));
    __nv_bfloat16 l1 = __float2bfloat16_rn(v1 - __bfloat162float(h1));
    *(uint32_t*)&g_bhi[hl][off] = bf2_pack(h0, h1);
    *(uint32_t*)&g_blo[hl][off] = bf2_pack(l0, l1);
}

// ======================= build kernels =====================================
__global__ void build_deg(const float* __restrict__ W) {
    int warp = (blockIdx.x * blockDim.x + threadIdx.x) >> 5;
    int lane = threadIdx.x & 31;
    if (warp >= DIM) return;
    float s = 0.f;
    const float* row = W + (size_t)warp * DIM;
    for (int d = lane; d < DIM; d += 32) s += fabsf(row[d]);
    #pragma unroll
    for (int o = 16; o > 0; o >>= 1) s += __shfl_down_sync(0xffffffffu, s, o);
    if (lane == 0) g_deg[warp] = fmaxf(s, 1e-8f);
}

__global__ void build_N(const float* __restrict__ W, const float* __restrict__ p) {
    int v = blockIdx.x * blockDim.x + threadIdx.x;
    if (v >= DIM * DIM / 2) return;
    int idx = v * 2;
    int e = idx >> 9;
    int d = idx & (DIM - 1);
    float m0 = fabsf(W[idx]) / g_deg[e];
    float m1 = fabsf(W[idx + 1]) / g_deg[e];
    if (e == d)     m0 -= (1.1f + p[d]);
    if (e == d + 1) m1 -= (1.1f + p[d + 1]);
    g_buf[BUF_N][idx]     = m0;
    g_buf[BUF_N][idx + 1] = m1;
    split_store(HB_N, idx, m0, m1);
}

// h (fp32) -> fp16 (read by the big GEMM)
__global__ void split_h(const float* __restrict__ h, int nvec) {
    int v = blockIdx.x * blockDim.x + threadIdx.x;   // float4 index
    if (v >= nvec) return;
    float4 x = ((const float4*)h)[v];
    int idx = v * 4;
    __half2 a = __floats2half2_rn(x.x, x.y);
    __half2 b = __floats2half2_rn(x.z, x.w);
    *(uint2*)&g_hf[idx] = make_uint2(*(uint32_t*)&a, *(uint32_t*)&b);
}

__global__ __launch_bounds__(256)
void build_D(const float* __restrict__ p, Coef cf) {
    int v = blockIdx.x * blockDim.x + threadIdx.x;
    if (v >= DIM * DIM / 2) return;
    int idx = v * 2;
    int e = idx >> 9;
    int d = idx & (DIM - 1);
    float r[3][2];
    #pragma unroll
    for (int u = 0; u < 2; u++) {
        int dd = d + u;
        float x0 = (e == dd) ? 1.f : 0.f;
        float x1 = g_buf[BUF_N ][idx + u];
        float x2 = g_buf[BUF_N2][idx + u];
        float x3 = g_buf[BUF_N3][idx + u];
        float pd = p[dd];
        #pragma unroll
        for (int j = 0; j < 3; j++) {
            float vp = cf.P[j][0] * x0 + cf.P[j][1] * x1 + cf.P[j][2] * x2 + cf.P[j][3] * x3;
            float vq = cf.Q[j][0] * x0 + cf.Q[j][1] * x1 + cf.Q[j][2] * x2 + cf.Q[j][3] * x3;
            r[j][u] = vp + vq * pd;
        }
    }
    g_buf[BUF_D0][idx]     = r[0][0];
    g_buf[BUF_D0][idx + 1] = r[0][1];
    g_buf[BUF_D1][idx]     = r[1][0];
    g_buf[BUF_D1][idx + 1] = r[1][1];
    split_store(HB_D2, idx, r[2][0], r[2][1]);
}

// ======================= mma.sync 512^3 GEMM (cp.async pipelined) ==========
// C = A(hi/lo) @ B(hi/lo); CTA 32x64, grid (16,8,z), 8 warps (2x4), warp
// tile 16x16. 128 CTAs/job (R12 used 64x64 tiles -> 64 CTAs, half the chip
// idle and 48% HMMA util on the active half).
// mode 0: plain; 1: += g_buf[addi]; 2: g*(C+g_buf[addi]) + (1-g)I.
// outf16: also write fp16 H matrix for the big GEMM.
#define APAD 40
#define BPAD 72

__global__ __launch_bounds__(256, 1)
void mma512(Job j0, Job j1, const float* __restrict__ ga) {
    __shared__ __align__(16) uint16_t Ahi[2][32][APAD];
    __shared__ __align__(16) uint16_t Alo[2][32][APAD];
    __shared__ __align__(16) uint16_t Bhi[2][32][BPAD];
    __shared__ __align__(16) uint16_t Blo[2][32][BPAD];

    const Job j = (blockIdx.z == 0) ? j0 : j1;
    const int tid  = threadIdx.x;
    const int wid  = tid >> 5;
    const int lane = tid & 31;
    const int wr = wid & 1;         // 16-row half
    const int wc = wid >> 1;        // 16-col quarter
    const int brow = blockIdx.x * 32;
    const int bcol = blockIdx.y * 64;

    const __nv_bfloat16* __restrict__ Ah = g_bhi[j.ahl];
    const __nv_bfloat16* __restrict__ Al = g_blo[j.ahl];
    const __nv_bfloat16* __restrict__ Bh = g_bhi[j.bhl];
    const __nv_bfloat16* __restrict__ Bl = g_blo[j.bhl];

    float acc[2][4];                // [ntile][frag]
    #pragma unroll
    for (int jj = 0; jj < 2; jj++)
        #pragma unroll
        for (int q = 0; q < 4; q++) acc[jj][q] = 0.f;

    const int aRow = wr * 16 + (lane & 15);
    const int aKp  = (lane >> 4) * 8;
    const int bLn  = lane & 15;
    // loaders: A (32 rows x 4 16B-chunks = 128 slots; tid<128 -> hi, else lo)
    const int lar = (tid & 127) >> 2, laq = tid & 3;
    // B: 32 k-rows x 8 16B-chunks = 256 slots, each thread does hi+lo
    const int lbr = tid >> 3, lbq = tid & 7;

    // prologue: chunk 0 -> buffer 0
    if (tid < 128)
        cp16(smem_u32(&Ahi[0][lar][laq * 8]), &Ah[(size_t)(brow + lar) * DIM + laq * 8]);
    else
        cp16(smem_u32(&Alo[0][lar][laq * 8]), &Al[(size_t)(brow + lar) * DIM + laq * 8]);
    cp16(smem_u32(&Bhi[0][lbr][lbq * 8]), &Bh[(size_t)lbr * DIM + bcol + lbq * 8]);
    cp16(smem_u32(&Blo[0][lbr][lbq * 8]), &Bl[(size_t)lbr * DIM + bcol + lbq * 8]);
    CP_COMMIT();

    for (int ch = 0; ch < 16; ch++) {
        if (ch + 1 < 16) {
            const int nb = (ch + 1) & 1;
            const int nk = (ch + 1) * 32;
            if (tid < 128)
                cp16(smem_u32(&Ahi[nb][lar][laq * 8]), &Ah[(size_t)(brow + lar) * DIM + nk + laq * 8]);
            else
                cp16(smem_u32(&Alo[nb][lar][laq * 8]), &Al[(size_t)(brow + lar) * DIM + nk + laq * 8]);
            cp16(smem_u32(&Bhi[nb][lbr][lbq * 8]), &Bh[(size_t)(nk + lbr) * DIM + bcol + lbq * 8]);
            cp16(smem_u32(&Blo[nb][lbr][lbq * 8]), &Bl[(size_t)(nk + lbr) * DIM + bcol + lbq * 8]);
            CP_COMMIT();
            CP_WAIT1();
        } else {
            CP_WAIT0();
        }
        __syncthreads();

        const int pb = ch & 1;
        const uint32_t ahB = smem_u32(&Ahi[pb][0][0]);
        const uint32_t alB = smem_u32(&Alo[pb][0][0]);
        const uint32_t bhB = smem_u32(&Bhi[pb][0][0]);
        const uint32_t blB = smem_u32(&Blo[pb][0][0]);

        #pragma unroll
        for (int ks = 0; ks < 2; ks++) {
            const int kk = ks * 16;
            uint32_t ah[4], al[4], bh[2][2], bl[2][2];
            {
                uint32_t ao = ((uint32_t)(aRow * APAD + kk + aKp)) * 2;
                ldm_x4(ah[0], ah[1], ah[2], ah[3], ahB + ao);
                ldm_x4(al[0], al[1], al[2], al[3], alB + ao);
            }
            #pragma unroll
            for (int nt = 0; nt < 2; nt++) {
                uint32_t bo = ((uint32_t)((kk + bLn) * BPAD + wc * 16 + nt * 8)) * 2;
                ldm_x2t(bh[nt][0], bh[nt][1], bhB + bo);
                ldm_x2t(bl[nt][0], bl[nt][1], blB + bo);
            }
            #pragma unroll
            for (int nt = 0; nt < 2; nt++) {
                mma_bf16(acc[nt], ah, bh[nt]);
                mma_bf16(acc[nt], ah, bl[nt]);
                mma_bf16(acc[nt], al, bh[nt]);
            }
        }
        __syncthreads();
    }

    const float g = (j.mode == 2) ? tanhf(ga[0]) : 0.f;
    const float omg = 1.0f - g;
    const int er0 = brow + wr * 16 + (lane >> 2);
    const int ec0 = bcol + wc * 16 + (lane & 3) * 2;

    #pragma unroll
    for (int nt = 0; nt < 2; nt++) {
        #pragma unroll
        for (int half = 0; half < 2; half++) {
            int r = er0 + half * 8;
            int c = ec0 + nt * 8;
            int off = r * DIM + c;
            float v0 = acc[nt][half * 2 + 0];
            float v1 = acc[nt][half * 2 + 1];
            if (j.mode == 1) {
                v0 += g_buf[j.addi][off];
                v1 += g_buf[j.addi][off + 1];
            } else if (j.mode == 2) {
                v0 = g * (v0 + g_buf[j.addi][off])     + ((r == c)     ? omg : 0.f);
                v1 = g * (v1 + g_buf[j.addi][off + 1]) + ((r == c + 1) ? omg : 0.f);
            }
            if (j.outfp >= 0) *(float2*)&g_buf[j.outfp][off] = make_float2(v0, v1);
            if (j.outhl >= 0) split_store(j.outhl, off, v0, v1);
            if (j.outf16) {
                __half2 hv = __floats2half2_rn(v0, v1);
                *(uint32_t*)&g_Hf[off] = *(uint32_t*)&hv;
            }
        }
    }
}

// ======================= big GEMM: fp16 single-product (proven R12) ========
// out[r, e] = sum_d h[r, d] * H[e, d]; A = g_hf, B = g_Hf (both fp16).
// CTA 128x128, grid (R/128, 4), 8 warps (2x4), warp 64x32; BK=32 chunks.
__global__ __launch_bounds__(256)
void mma_gemm3(float* __restrict__ out) {
    __shared__ __align__(16) uint16_t As[2][128][APAD];
    __shared__ __align__(16) uint16_t Bs[2][128][APAD];

    const int tid  = threadIdx.x;
    const int wid  = tid >> 5;
    const int lane = tid & 31;
    const int wr = wid & 1;
    const int wc = wid >> 1;
    const int brow = blockIdx.x * 128;
    const int bcol = blockIdx.y * 128;

    float acc[4][4][4];
    #pragma unroll
    for (int i = 0; i < 4; i++)
        #pragma unroll
        for (int jj = 0; jj < 4; jj++)
            #pragma unroll
            for (int q = 0; q < 4; q++) acc[i][jj][q] = 0.f;

    const int aRow = wr * 64 + (lane & 15);
    const int aKp  = (lane >> 4) * 8;
    const int bRow = wc * 32 + (lane & 7);
    const int bKp  = ((lane >> 3) & 1) * 8;
    const int lr0 = tid >> 2, lq0 = tid & 3;

    #pragma unroll
    for (int i = 0; i < 2; i++) {
        int row = lr0 + i * 64;
        cp16(smem_u32(&As[0][row][lq0 * 8]), &g_hf[(size_t)(brow + row) * DIM + lq0 * 8]);
        cp16(smem_u32(&Bs[0][row][lq0 * 8]), &g_Hf[(size_t)(bcol + row) * DIM + lq0 * 8]);
    }
    CP_COMMIT();

    for (int ch = 0; ch < 16; ch++) {
        if (ch + 1 < 16) {
            const int nb = (ch + 1) & 1;
            const int nk = (ch + 1) * 32;
            #pragma unroll
            for (int i = 0; i < 2; i++) {
                int row = lr0 + i * 64;
                cp16(smem_u32(&As[nb][row][lq0 * 8]), &g_hf[(size_t)(brow + row) * DIM + nk + lq0 * 8]);
                cp16(smem_u32(&Bs[nb][row][lq0 * 8]), &g_Hf[(size_t)(bcol + row) * DIM + nk + lq0 * 8]);
            }
            CP_COMMIT();
            CP_WAIT1();
        } else {
            CP_WAIT0();
        }
        __syncthreads();

        const int pb = ch & 1;
        const uint32_t aB = smem_u32(&As[pb][0][0]);
        const uint32_t bB = smem_u32(&Bs[pb][0][0]);

        #pragma unroll
        for (int ks = 0; ks < 2; ks++) {
            const int kk = ks * 16;
            uint32_t af[4][4], bf[4][2];
            #pragma unroll
            for (int mt = 0; mt < 4; mt++) {
                uint32_t ao = ((uint32_t)((aRow + mt * 16) * APAD + kk + aKp)) * 2;
                ldm_x4(af[mt][0], af[mt][1], af[mt][2], af[mt][3], aB + ao);
            }
            #pragma unroll
            for (int nt = 0; nt < 4; nt++) {
                uint32_t bo = ((uint32_t)((bRow + nt * 8) * APAD + kk + bKp)) * 2;
                ldm_x2(bf[nt][0], bf[nt][1], bB + bo);
            }
            #pragma unroll
            for (int mt = 0; mt < 4; mt++)
                #pragma unroll
                for (int nt = 0; nt < 4; nt++)
                    mma_f16(acc[mt][nt], af[mt], bf[nt]);
        }
        __syncthreads();
    }

    const int er = brow + wr * 64 + (lane >> 2);
    const int ec = bcol + wc * 32 + (lane & 3) * 2;
    #pragma unroll
    for (int mt = 0; mt < 4; mt++) {
        #pragma unroll
        for (int nt = 0; nt < 4; nt++) {
            float* p0 = out + (size_t)(er + mt * 16) * DIM + ec + nt * 8;
            *(float2*)p0 = make_float2(acc[mt][nt][0], acc[mt][nt][1]);
            float* p1 = out + (size_t)(er + mt * 16 + 8) * DIM + ec + nt * 8;
            *(float2*)p1 = make_float2(acc[mt][nt][2], acc[mt][nt][3]);
        }
    }
}

// ---------------------------------------------------------------------------
extern "C" void kernel_launch(void* const* d_in, const int* in_sizes, int n_in,
                              void* d_out, int out_size) {
    const float* h  = (const float*)d_in[0];
    const float* W  = (const float*)d_in[1];
    const float* ga = (const float*)d_in[2];
    const float* p  = (const float*)d_in[3];
    float* out = (float*)d_out;

    const int R = in_sizes[0] / DIM;          // B*S = 16384

    // host-side polynomial coefficients (doubles; deterministic)
    double Ac[12] = {0}, Bc[12] = {0}, Cc[12] = {0}, Dc[12] = {0};
    Ac[0] = 1.0;
    {
        const double dt = 0.1, beta = 2.0 * sqrt(2.1), c1 = 1.0 - dt * beta;
        for (int n = 0; n < 10; n++) {
            double Cn[12], Dn[12];
            for (int k = 0; k < 12; k++) {
                Cn[k] = c1 * Cc[k] + (k > 0 ? dt * Ac[k - 1] : 0.0);
                Dn[k] = c1 * Dc[k] + (k > 0 ? dt * Bc[k - 1] : 0.0);
            }
            Dn[0] += dt;
            for (int k = 0; k < 12; k++) {
                Cc[k] = Cn[k];  Dc[k] = Dn[k];
                Ac[k] += dt * Cn[k];
                Bc[k] += dt * Dn[k];
            }
        }
    }
    Coef cf;
    for (int j = 0; j < 3; j++)
        for (int m = 0; m < 4; m++) {
            cf.P[j][m] = (float)Ac[4 * j + m];
            cf.Q[j][m] = (float)Bc[4 * j + m];
        }

    const int PAIR_BLKS = (DIM * DIM / 2 + 255) / 256;
    const int HVEC = R * DIM / 4;

    build_deg<<<(DIM * 32 + 255) / 256, 256>>>(W);
    build_N<<<PAIR_BLKS, 256>>>(W, p);
    split_h<<<(HVEC + 255) / 256, 256>>>(h, HVEC);

    Job jN2 = {HB_N,  HB_N,  0, 0,      BUF_N2, HB_N2, 0};
    Job jN3 = {HB_N,  HB_N2, 0, 0,      BUF_N3, -1,    0};
    Job jN4 = {HB_N2, HB_N2, 0, 0,      -1,     HB_N4, 0};
    Job jE  = {HB_N4, HB_D2, 1, BUF_D1, -1,     HB_E,  0};
    Job jH  = {HB_N4, HB_E,  2, BUF_D0, -1,     -1,    1};

    mma512<<<dim3(16, 8, 1), 256>>>(jN2, jN2, ga);       // N2
    mma512<<<dim3(16, 8, 2), 256>>>(jN3, jN4, ga);       // N3 + N4 (merged)
    build_D<<<PAIR_BLKS, 256>>>(p, cf);
    mma512<<<dim3(16, 8, 1), 256>>>(jE, jE, ga);         // E = N4*D2 + D1
    mma512<<<dim3(16, 8, 1), 256>>>(jH, jH, ga);         // H (emits fp16)

    mma_gemm3<<<dim3(R / 128, DIM / 128), 256>>>(out);
}

// round 14
// speedup vs baseline: 2.1224x; 1.0408x over previous
#include <cuda_runtime.h>
#include <cuda_bf16.h>
#include <cuda_fp16.h>
#include <math.h>
#include <cstdint>

// ---------------------------------------------------------------------------
// SOMI settling layer — Paterson-Stockmeyer collapsed formulation.
//   N = |W|/deg - (1.1 + p) on diag;  H = (1-g)I + g*(D0 + N^4(D1 + N^4 D2))
//   out = H @ h over the hidden dim.
// Poly chain: mma.sync bf16 hi/lo 3-product, 32x64 CTA tiles, BK=64.
// Big GEMM: mma.sync fp16 single-product, 128x128 CTA tiles, BK=64.
//
// HARD RULES LEARNED:
//  R3/R4: never pass __device__ global symbols as host-side kernel args.
//  R6:    harness compiles baseline sm_100 -> no tcgen05/TMEM; mma.sync only.
//  R9:    single-buffered smem mma loops are ~90% stalled -> cp.async pipeline.
//  R11:   big GEMM hit the mma.sync compute floor -> fp16 single product.
//  R13:   16-chunk loops are barrier/ldmatrix latency-bound -> BK=64.
// ---------------------------------------------------------------------------

#define DIM 512
#define RMAX (4 * 4096)

// fp32 arena ids
#define BUF_N   0
#define BUF_N2  1
#define BUF_N3  2
#define BUF_D0  3
#define BUF_D1  4
// bf16 hi/lo arena ids
#define HB_N    0
#define HB_N2   1
#define HB_N4   2
#define HB_D2   3
#define HB_E    4

__device__ __align__(16) float g_deg[DIM];
__device__ __align__(16) float g_buf[5][DIM * DIM];
__device__ __align__(16) __nv_bfloat16 g_bhi[5][DIM * DIM];
__device__ __align__(16) __nv_bfloat16 g_blo[5][DIM * DIM];
__device__ __align__(16) __half g_Hf[DIM * DIM];      // H in fp16 (big GEMM B)
__device__ __align__(16) __half g_hf[RMAX * DIM];     // h in fp16 (big GEMM A)

struct Coef { float P[3][4]; float Q[3][4]; };
struct Job  { int ahl, bhl, mode, addi, outfp, outhl, outf16; };

// ======================= helpers ===========================================
__device__ __forceinline__ uint32_t smem_u32(const void* p) {
    uint32_t a;
    asm("{ .reg .u64 t; cvta.to.shared.u64 t, %1; cvt.u32.u64 %0, t; }"
        : "=r"(a) : "l"(p));
    return a;
}
__device__ __forceinline__ uint32_t bf2_pack(__nv_bfloat16 a, __nv_bfloat16 b) {
    __nv_bfloat162 t = __halves2bfloat162(a, b);
    return *reinterpret_cast<uint32_t*>(&t);
}
__device__ __forceinline__ void cp16(uint32_t dst, const void* src) {
    asm volatile("cp.async.cg.shared.global [%0], [%1], 16;"
                 :: "r"(dst), "l"(src) : "memory");
}
#define CP_COMMIT() asm volatile("cp.async.commit_group;" ::: "memory")
#define CP_WAIT1()  asm volatile("cp.async.wait_group 1;" ::: "memory")
#define CP_WAIT0()  asm volatile("cp.async.wait_group 0;" ::: "memory")

__device__ __forceinline__ void ldm_x4(uint32_t& r0, uint32_t& r1,
                                       uint32_t& r2, uint32_t& r3, uint32_t a) {
    asm volatile("ldmatrix.sync.aligned.m8n8.x4.shared.b16 {%0,%1,%2,%3}, [%4];"
                 : "=r"(r0), "=r"(r1), "=r"(r2), "=r"(r3) : "r"(a));
}
__device__ __forceinline__ void ldm_x2(uint32_t& r0, uint32_t& r1, uint32_t a) {
    asm volatile("ldmatrix.sync.aligned.m8n8.x2.shared.b16 {%0,%1}, [%2];"
                 : "=r"(r0), "=r"(r1) : "r"(a));
}
__device__ __forceinline__ void ldm_x2t(uint32_t& r0, uint32_t& r1, uint32_t a) {
    asm volatile("ldmatrix.sync.aligned.m8n8.x2.trans.shared.b16 {%0,%1}, [%2];"
                 : "=r"(r0), "=r"(r1) : "r"(a));
}
__device__ __forceinline__ void mma_bf16(float* c, const uint32_t* a,
                                         const uint32_t* b) {
    asm volatile(
        "mma.sync.aligned.m16n8k16.row.col.f32.bf16.bf16.f32 "
        "{%0,%1,%2,%3}, {%4,%5,%6,%7}, {%8,%9}, {%0,%1,%2,%3};"
        : "+f"(c[0]), "+f"(c[1]), "+f"(c[2]), "+f"(c[3])
        : "r"(a[0]), "r"(a[1]), "r"(a[2]), "r"(a[3]), "r"(b[0]), "r"(b[1]));
}
__device__ __forceinline__ void mma_f16(float* c, const uint32_t* a,
                                        const uint32_t* b) {
    asm volatile(
        "mma.sync.aligned.m16n8k16.row.col.f32.f16.f16.f32 "
        "{%0,%1,%2,%3}, {%4,%5,%6,%7}, {%8,%9}, {%0,%1,%2,%3};"
        : "+f"(c[0]), "+f"(c[1]), "+f"(c[2]), "+f"(c[3])
        : "r"(a[0]), "r"(a[1]), "r"(a[2]), "r"(a[3]), "r"(b[0]), "r"(b[1]));
}
__device__ __forceinline__ void split_store(int hl, int off, float v0, float v1) {
    __nv_bfloat16 h0 = __float2bfloat16_rn(v0);
    __nv_bfloat16 h1 = __float2bfloat16_rn(v1);
    __nv_bfloat16 l0 = __float2bfloat16_rn(v0 - __bfloat162float(h0));
    __nv_bfloat16 l1 = __float2bfloat16_rn(v1 - __bfloat162float(h1));
    *(uint32_t*)&g_bhi[hl][off] = bf2_pack(h0, h1);
    *(uint32_t*)&g_blo[hl][off] = bf2_pack(l0, l1);
}

// ======================= build kernels =====================================
__global__ void build_deg(const float* __restrict__ W) {
    int warp = (blockIdx.x * blockDim.x + threadIdx.x) >> 5;
    int lane = threadIdx.x & 31;
    if (warp >= DIM) return;
    float s = 0.f;
    const float* row = W + (size_t)warp * DIM;
    for (int d = lane; d < DIM; d += 32) s += fabsf(row[d]);
    #pragma unroll
    for (int o = 16; o > 0; o >>= 1) s += __shfl_down_sync(0xffffffffu, s, o);
    if (lane == 0) g_deg[warp] = fmaxf(s, 1e-8f);
}

__global__ void build_N(const float* __restrict__ W, const float* __restrict__ p) {
    int v = blockIdx.x * blockDim.x + threadIdx.x;
    if (v >= DIM * DIM / 2) return;
    int idx = v * 2;
    int e = idx >> 9;
    int d = idx & (DIM - 1);
    float m0 = fabsf(W[idx]) / g_deg[e];
    float m1 = fabsf(W[idx + 1]) / g_deg[e];
    if (e == d)     m0 -= (1.1f + p[d]);
    if (e == d + 1) m1 -= (1.1f + p[d + 1]);
    g_buf[BUF_N][idx]     = m0;
    g_buf[BUF_N][idx + 1] = m1;
    split_store(HB_N, idx, m0, m1);
}

// h (fp32) -> fp16 (read by the big GEMM)
__global__ void split_h(const float* __restrict__ h, int nvec) {
    int v = blockIdx.x * blockDim.x + threadIdx.x;
    if (v >= nvec) return;
    float4 x = ((const float4*)h)[v];
    int idx = v * 4;
    __half2 a = __floats2half2_rn(x.x, x.y);
    __half2 b = __floats2half2_rn(x.z, x.w);
    *(uint2*)&g_hf[idx] = make_uint2(*(uint32_t*)&a, *(uint32_t*)&b);
}

__global__ __launch_bounds__(256)
void build_D(const float* __restrict__ p, Coef cf) {
    int v = blockIdx.x * blockDim.x + threadIdx.x;
    if (v >= DIM * DIM / 2) return;
    int idx = v * 2;
    int e = idx >> 9;
    int d = idx & (DIM - 1);
    float r[3][2];
    #pragma unroll
    for (int u = 0; u < 2; u++) {
        int dd = d + u;
        float x0 = (e == dd) ? 1.f : 0.f;
        float x1 = g_buf[BUF_N ][idx + u];
        float x2 = g_buf[BUF_N2][idx + u];
        float x3 = g_buf[BUF_N3][idx + u];
        float pd = p[dd];
        #pragma unroll
        for (int j = 0; j < 3; j++) {
            float vp = cf.P[j][0] * x0 + cf.P[j][1] * x1 + cf.P[j][2] * x2 + cf.P[j][3] * x3;
            float vq = cf.Q[j][0] * x0 + cf.Q[j][1] * x1 + cf.Q[j][2] * x2 + cf.Q[j][3] * x3;
            r[j][u] = vp + vq * pd;
        }
    }
    g_buf[BUF_D0][idx]     = r[0][0];
    g_buf[BUF_D0][idx + 1] = r[0][1];
    g_buf[BUF_D1][idx]     = r[1][0];
    g_buf[BUF_D1][idx + 1] = r[1][1];
    split_store(HB_D2, idx, r[2][0], r[2][1]);
}

// ======================= mma.sync 512^3 GEMM (BK=64, dyn smem) =============
// C = A(hi/lo) @ B(hi/lo); CTA 32x64, grid (16,8,z), 8 warps (2x4), warp
// tile 16x16, BK=64 -> 8 chunks (24 MMAs/warp per barrier interval).
// Dynamic smem layout (54KB):
//   AHI @0      2 bufs x 32 x 72 bf16  (buf stride 4608 B)
//   ALO @9216   same
//   BHI @18432  2 bufs x 64 x 72 bf16  (buf stride 9216 B)
//   BLO @36864  same                    total 55296 B
#define M5_AHI 0
#define M5_ALO 9216
#define M5_BHI 18432
#define M5_BLO 36864
#define M5_TOT 55296
#define M5_ABUF 4608
#define M5_BBUF 9216
#define KPAD 72

__global__ __launch_bounds__(256, 1)
void mma512(Job j0, Job j1, const float* __restrict__ ga) {
    extern __shared__ char dsm[];
    const uint32_t sb = smem_u32(dsm);

    const Job j = (blockIdx.z == 0) ? j0 : j1;
    const int tid  = threadIdx.x;
    const int wid  = tid >> 5;
    const int lane = tid & 31;
    const int wr = wid & 1;
    const int wc = wid >> 1;
    const int brow = blockIdx.x * 32;
    const int bcol = blockIdx.y * 64;

    const __nv_bfloat16* __restrict__ Ah = g_bhi[j.ahl];
    const __nv_bfloat16* __restrict__ Al = g_blo[j.ahl];
    const __nv_bfloat16* __restrict__ Bh = g_bhi[j.bhl];
    const __nv_bfloat16* __restrict__ Bl = g_blo[j.bhl];

    float acc[2][4];
    #pragma unroll
    for (int jj = 0; jj < 2; jj++)
        #pragma unroll
        for (int q = 0; q < 4; q++) acc[jj][q] = 0.f;

    const int aRow = wr * 16 + (lane & 15);
    const int aKp  = (lane >> 4) * 8;
    const int bLn  = lane & 15;
    // loaders: A 32 rows x 8 16B-chunks = 256 slots (1/thread, hi + lo)
    const int lar = tid >> 3, laq = tid & 7;
    // B: 64 k-rows x 8 16B-chunks = 512 slots (2/thread, hi + lo)

    // prologue: chunk 0 -> buffer 0
    {
        uint32_t ad = sb + (uint32_t)((lar * KPAD + laq * 8) * 2);
        cp16(ad + M5_AHI, &Ah[(size_t)(brow + lar) * DIM + laq * 8]);
        cp16(ad + M5_ALO, &Al[(size_t)(brow + lar) * DIM + laq * 8]);
        #pragma unroll
        for (int i = 0; i < 2; i++) {
            int s = tid + i * 256;
            int br = s >> 3, bq = s & 7;
            uint32_t bd = sb + (uint32_t)((br * KPAD + bq * 8) * 2);
            cp16(bd + M5_BHI, &Bh[(size_t)br * DIM + bcol + bq * 8]);
            cp16(bd + M5_BLO, &Bl[(size_t)br * DIM + bcol + bq * 8]);
        }
    }
    CP_COMMIT();

    for (int ch = 0; ch < 8; ch++) {
        if (ch + 1 < 8) {
            const int nb = (ch + 1) & 1;
            const int nk = (ch + 1) * 64;
            uint32_t ad = sb + (uint32_t)(nb * M5_ABUF + (lar * KPAD + laq * 8) * 2);
            cp16(ad + M5_AHI, &Ah[(size_t)(brow + lar) * DIM + nk + laq * 8]);
            cp16(ad + M5_ALO, &Al[(size_t)(brow + lar) * DIM + nk + laq * 8]);
            #pragma unroll
            for (int i = 0; i < 2; i++) {
                int s = tid + i * 256;
                int br = s >> 3, bq = s & 7;
                uint32_t bd = sb + (uint32_t)(nb * M5_BBUF + (br * KPAD + bq * 8) * 2);
                cp16(bd + M5_BHI, &Bh[(size_t)(nk + br) * DIM + bcol + bq * 8]);
                cp16(bd + M5_BLO, &Bl[(size_t)(nk + br) * DIM + bcol + bq * 8]);
            }
            CP_COMMIT();
            CP_WAIT1();
        } else {
            CP_WAIT0();
        }
        __syncthreads();

        const int pb = ch & 1;
        const uint32_t aBase = sb + (uint32_t)(pb * M5_ABUF);
        const uint32_t bBase = sb + (uint32_t)(pb * M5_BBUF);

        #pragma unroll
        for (int ks = 0; ks < 4; ks++) {
            const int kk = ks * 16;
            uint32_t ah[4], al[4], bh[2][2], bl[2][2];
            {
                uint32_t ao = ((uint32_t)(aRow * KPAD + kk + aKp)) * 2;
                ldm_x4(ah[0], ah[1], ah[2], ah[3], aBase + M5_AHI + ao);
                ldm_x4(al[0], al[1], al[2], al[3], aBase + M5_ALO + ao);
            }
            #pragma unroll
            for (int nt = 0; nt < 2; nt++) {
                uint32_t bo = ((uint32_t)((kk + bLn) * KPAD + wc * 16 + nt * 8)) * 2;
                ldm_x2t(bh[nt][0], bh[nt][1], bBase + M5_BHI + bo);
                ldm_x2t(bl[nt][0], bl[nt][1], bBase + M5_BLO + bo);
            }
            #pragma unroll
            for (int nt = 0; nt < 2; nt++) {
                mma_bf16(acc[nt], ah, bh[nt]);
                mma_bf16(acc[nt], ah, bl[nt]);
                mma_bf16(acc[nt], al, bh[nt]);
            }
        }
        __syncthreads();
    }

    const float g = (j.mode == 2) ? tanhf(ga[0]) : 0.f;
    const float omg = 1.0f - g;
    const int er0 = brow + wr * 16 + (lane >> 2);
    const int ec0 = bcol + wc * 16 + (lane & 3) * 2;

    #pragma unroll
    for (int nt = 0; nt < 2; nt++) {
        #pragma unroll
        for (int half = 0; half < 2; half++) {
            int r = er0 + half * 8;
            int c = ec0 + nt * 8;
            int off = r * DIM + c;
            float v0 = acc[nt][half * 2 + 0];
            float v1 = acc[nt][half * 2 + 1];
            if (j.mode == 1) {
                v0 += g_buf[j.addi][off];
                v1 += g_buf[j.addi][off + 1];
            } else if (j.mode == 2) {
                v0 = g * (v0 + g_buf[j.addi][off])     + ((r == c)     ? omg : 0.f);
                v1 = g * (v1 + g_buf[j.addi][off + 1]) + ((r == c + 1) ? omg : 0.f);
            }
            if (j.outfp >= 0) *(float2*)&g_buf[j.outfp][off] = make_float2(v0, v1);
            if (j.outhl >= 0) split_store(j.outhl, off, v0, v1);
            if (j.outf16) {
                __half2 hv = __floats2half2_rn(v0, v1);
                *(uint32_t*)&g_Hf[off] = *(uint32_t*)&hv;
            }
        }
    }
}

// ======================= big GEMM: fp16, BK=64, dyn smem ===================
// out[r, e] = sum_d h[r, d] * H[e, d]; A = g_hf, B = g_Hf (both fp16).
// CTA 128x128, grid (R/128, 4), 8 warps (2x4), warp 64x32, BK=64 -> 8 chunks.
// Dynamic smem: As @0, Bs @36864; each 2 bufs x 128 x 72 fp16 (buf stride
// 18432 B); total 73728 B.
#define MG_AS   0
#define MG_BS   36864
#define MG_TOT  73728
#define MG_BUFS 18432

__global__ __launch_bounds__(256)
void mma_gemm3(float* __restrict__ out) {
    extern __shared__ char dsm[];
    const uint32_t sb = smem_u32(dsm);

    const int tid  = threadIdx.x;
    const int wid  = tid >> 5;
    const int lane = tid & 31;
    const int wr = wid & 1;
    const int wc = wid >> 1;
    const int brow = blockIdx.x * 128;
    const int bcol = blockIdx.y * 128;

    float acc[4][4][4];
    #pragma unroll
    for (int i = 0; i < 4; i++)
        #pragma unroll
        for (int jj = 0; jj < 4; jj++)
            #pragma unroll
            for (int q = 0; q < 4; q++) acc[i][jj][q] = 0.f;

    const int aRow = wr * 64 + (lane & 15);
    const int aKp  = (lane >> 4) * 8;
    const int bRow = wc * 32 + (lane & 7);
    const int bKp  = ((lane >> 3) & 1) * 8;
    const int lr0 = tid >> 3, lq0 = tid & 7;   // 128 rows x 8 chunks = 1024 slots, 4/thread

    // prologue
    #pragma unroll
    for (int i = 0; i < 4; i++) {
        int s = tid + i * 256;
        int row = s >> 3, q = s & 7;
        uint32_t d0 = sb + (uint32_t)((row * KPAD + q * 8) * 2);
        cp16(d0 + MG_AS, &g_hf[(size_t)(brow + row) * DIM + q * 8]);
        cp16(d0 + MG_BS, &g_Hf[(size_t)(bcol + row) * DIM + q * 8]);
    }
    CP_COMMIT();

    for (int ch = 0; ch < 8; ch++) {
        if (ch + 1 < 8) {
            const int nb = (ch + 1) & 1;
            const int nk = (ch + 1) * 64;
            #pragma unroll
            for (int i = 0; i < 4; i++) {
                int s = tid + i * 256;
                int row = s >> 3, q = s & 7;
                uint32_t d0 = sb + (uint32_t)(nb * MG_BUFS + (row * KPAD + q * 8) * 2);
                cp16(d0 + MG_AS, &g_hf[(size_t)(brow + row) * DIM + nk + q * 8]);
                cp16(d0 + MG_BS, &g_Hf[(size_t)(bcol + row) * DIM + nk + q * 8]);
            }
            CP_COMMIT();
            CP_WAIT1();
        } else {
            CP_WAIT0();
        }
        __syncthreads();

        const uint32_t aB = sb + (uint32_t)((ch & 1) * MG_BUFS) + MG_AS;
        const uint32_t bB = sb + (uint32_t)((ch & 1) * MG_BUFS) + MG_BS;

        #pragma unroll
        for (int ks = 0; ks < 4; ks++) {
            const int kk = ks * 16;
            uint32_t af[4][4], bf[4][2];
            #pragma unroll
            for (int mt = 0; mt < 4; mt++) {
                uint32_t ao = ((uint32_t)((aRow + mt * 16) * KPAD + kk + aKp)) * 2;
                ldm_x4(af[mt][0], af[mt][1], af[mt][2], af[mt][3], aB + ao);
            }
            #pragma unroll
            for (int nt = 0; nt < 4; nt++) {
                uint32_t bo = ((uint32_t)((bRow + nt * 8) * KPAD + kk + bKp)) * 2;
                ldm_x2(bf[nt][0], bf[nt][1], bB + bo);
            }
            #pragma unroll
            for (int mt = 0; mt < 4; mt++)
                #pragma unroll
                for (int nt = 0; nt < 4; nt++)
                    mma_f16(acc[mt][nt], af[mt], bf[nt]);
        }
        __syncthreads();
    }

    const int er = brow + wr * 64 + (lane >> 2);
    const int ec = bcol + wc * 32 + (lane & 3) * 2;
    #pragma unroll
    for (int mt = 0; mt < 4; mt++) {
        #pragma unroll
        for (int nt = 0; nt < 4; nt++) {
            float* p0 = out + (size_t)(er + mt * 16) * DIM + ec + nt * 8;
            *(float2*)p0 = make_float2(acc[mt][nt][0], acc[mt][nt][1]);
            float* p1 = out + (size_t)(er + mt * 16 + 8) * DIM + ec + nt * 8;
            *(float2*)p1 = make_float2(acc[mt][nt][2], acc[mt][nt][3]);
        }
    }
}

// ---------------------------------------------------------------------------
extern "C" void kernel_launch(void* const* d_in, const int* in_sizes, int n_in,
                              void* d_out, int out_size) {
    const float* h  = (const float*)d_in[0];
    const float* W  = (const float*)d_in[1];
    const float* ga = (const float*)d_in[2];
    const float* p  = (const float*)d_in[3];
    float* out = (float*)d_out;

    const int R = in_sizes[0] / DIM;          // B*S = 16384

    // host-side polynomial coefficients (doubles; deterministic)
    double Ac[12] = {0}, Bc[12] = {0}, Cc[12] = {0}, Dc[12] = {0};
    Ac[0] = 1.0;
    {
        const double dt = 0.1, beta = 2.0 * sqrt(2.1), c1 = 1.0 - dt * beta;
        for (int n = 0; n < 10; n++) {
            double Cn[12], Dn[12];
            for (int k = 0; k < 12; k++) {
                Cn[k] = c1 * Cc[k] + (k > 0 ? dt * Ac[k - 1] : 0.0);
                Dn[k] = c1 * Dc[k] + (k > 0 ? dt * Bc[k - 1] : 0.0);
            }
            Dn[0] += dt;
            for (int k = 0; k < 12; k++) {
                Cc[k] = Cn[k];  Dc[k] = Dn[k];
                Ac[k] += dt * Cn[k];
                Bc[k] += dt * Dn[k];
            }
        }
    }
    Coef cf;
    for (int j = 0; j < 3; j++)
        for (int m = 0; m < 4; m++) {
            cf.P[j][m] = (float)Ac[4 * j + m];
            cf.Q[j][m] = (float)Bc[4 * j + m];
        }

    const int PAIR_BLKS = (DIM * DIM / 2 + 255) / 256;
    const int HVEC = R * DIM / 4;

    cudaFuncSetAttribute(mma512, cudaFuncAttributeMaxDynamicSharedMemorySize, M5_TOT);
    cudaFuncSetAttribute(mma_gemm3, cudaFuncAttributeMaxDynamicSharedMemorySize, MG_TOT);

    build_deg<<<(DIM * 32 + 255) / 256, 256>>>(W);
    build_N<<<PAIR_BLKS, 256>>>(W, p);
    split_h<<<(HVEC + 255) / 256, 256>>>(h, HVEC);

    Job jN2 = {HB_N,  HB_N,  0, 0,      BUF_N2, HB_N2, 0};
    Job jN3 = {HB_N,  HB_N2, 0, 0,      BUF_N3, -1,    0};
    Job jN4 = {HB_N2, HB_N2, 0, 0,      -1,     HB_N4, 0};
    Job jE  = {HB_N4, HB_D2, 1, BUF_D1, -1,     HB_E,  0};
    Job jH  = {HB_N4, HB_E,  2, BUF_D0, -1,     -1,    1};

    mma512<<<dim3(16, 8, 1), 256, M5_TOT>>>(jN2, jN2, ga);   // N2
    mma512<<<dim3(16, 8, 2), 256, M5_TOT>>>(jN3, jN4, ga);   // N3 + N4
    build_D<<<PAIR_BLKS, 256>>>(p, cf);
    mma512<<<dim3(16, 8, 1), 256, M5_TOT>>>(jE, jE, ga);     // E = N4*D2 + D1
    mma512<<<dim3(16, 8, 1), 256, M5_TOT>>>(jH, jH, ga);     // H (emits fp16)

    mma_gemm3<<<dim3(R / 128, DIM / 128), 256, MG_TOT>>>(out);
}

// round 15
// speedup vs baseline: 2.3119x; 1.0893x over previous
#include <cuda_runtime.h>
#include <cuda_bf16.h>
#include <cuda_fp16.h>
#include <math.h>
#include <cstdint>

// ---------------------------------------------------------------------------
// SOMI settling layer — Paterson-Stockmeyer collapsed formulation.
//   N = |W|/deg - (1.1 + p) on diag;  H = (1-g)I + g*(D0 + N^4(D1 + N^4 D2))
//   out = H @ h over the hidden dim.
// Poly chain: mma.sync bf16 hi/lo 3-product, 32x64 CTA / 4 warps / 4 accs per
// warp (R14's 8-warp 2-acc layout was accumulator-RAW latency-bound).
// Big GEMM: mma.sync fp16 single-product, 128x64 CTA -> 2 CTAs/SM.
//
// HARD RULES LEARNED:
//  R3/R4: never pass __device__ global symbols as host-side kernel args.
//  R6:    harness compiles baseline sm_100 -> no tcgen05/TMEM; mma.sync only.
//  R9:    single-buffered smem mma loops are ~90% stalled -> cp.async pipeline.
//  R11:   big GEMM hit the mma.sync compute floor -> fp16 single product.
//  R13:   16-chunk loops are barrier/ldmatrix latency-bound -> BK=64.
//  R14:   2 accumulators/warp -> MMA RAW chain bound -> 4 accs + occupancy.
// ---------------------------------------------------------------------------

#define DIM 512
#define RMAX (4 * 4096)

// fp32 arena ids
#define BUF_N   0
#define BUF_N2  1
#define BUF_N3  2
#define BUF_D0  3
#define BUF_D1  4
// bf16 hi/lo arena ids
#define HB_N    0
#define HB_N2   1
#define HB_N4   2
#define HB_D2   3
#define HB_E    4

__device__ __align__(16) float g_buf[5][DIM * DIM];
__device__ __align__(16) __nv_bfloat16 g_bhi[5][DIM * DIM];
__device__ __align__(16) __nv_bfloat16 g_blo[5][DIM * DIM];
__device__ __align__(16) __half g_Hf[DIM * DIM];      // H in fp16 (big GEMM B)
__device__ __align__(16) __half g_hf[RMAX * DIM];     // h in fp16 (big GEMM A)

struct Coef { float P[3][4]; float Q[3][4]; };
struct Job  { int ahl, bhl, mode, addi, outfp, outhl, outf16; };

// ======================= helpers ===========================================
__device__ __forceinline__ uint32_t smem_u32(const void* p) {
    uint32_t a;
    asm("{ .reg .u64 t; cvta.to.shared.u64 t, %1; cvt.u32.u64 %0, t; }"
        : "=r"(a) : "l"(p));
    return a;
}
__device__ __forceinline__ uint32_t bf2_pack(__nv_bfloat16 a, __nv_bfloat16 b) {
    __nv_bfloat162 t = __halves2bfloat162(a, b);
    return *reinterpret_cast<uint32_t*>(&t);
}
__device__ __forceinline__ void cp16(uint32_t dst, const void* src) {
    asm volatile("cp.async.cg.shared.global [%0], [%1], 16;"
                 :: "r"(dst), "l"(src) : "memory");
}
#define CP_COMMIT() asm volatile("cp.async.commit_group;" ::: "memory")
#define CP_WAIT1()  asm volatile("cp.async.wait_group 1;" ::: "memory")
#define CP_WAIT0()  asm volatile("cp.async.wait_group 0;" ::: "memory")

__device__ __forceinline__ void ldm_x4(uint32_t& r0, uint32_t& r1,
                                       uint32_t& r2, uint32_t& r3, uint32_t a) {
    asm volatile("ldmatrix.sync.aligned.m8n8.x4.shared.b16 {%0,%1,%2,%3}, [%4];"
                 : "=r"(r0), "=r"(r1), "=r"(r2), "=r"(r3) : "r"(a));
}
__device__ __forceinline__ void ldm_x2(uint32_t& r0, uint32_t& r1, uint32_t a) {
    asm volatile("ldmatrix.sync.aligned.m8n8.x2.shared.b16 {%0,%1}, [%2];"
                 : "=r"(r0), "=r"(r1) : "r"(a));
}
__device__ __forceinline__ void ldm_x4t(uint32_t& r0, uint32_t& r1,
                                        uint32_t& r2, uint32_t& r3, uint32_t a) {
    asm volatile("ldmatrix.sync.aligned.m8n8.x4.trans.shared.b16 {%0,%1,%2,%3}, [%4];"
                 : "=r"(r0), "=r"(r1), "=r"(r2), "=r"(r3) : "r"(a));
}
__device__ __forceinline__ void mma_bf16(float* c, const uint32_t* a,
                                         const uint32_t* b) {
    asm volatile(
        "mma.sync.aligned.m16n8k16.row.col.f32.bf16.bf16.f32 "
        "{%0,%1,%2,%3}, {%4,%5,%6,%7}, {%8,%9}, {%0,%1,%2,%3};"
        : "+f"(c[0]), "+f"(c[1]), "+f"(c[2]), "+f"(c[3])
        : "r"(a[0]), "r"(a[1]), "r"(a[2]), "r"(a[3]), "r"(b[0]), "r"(b[1]));
}
__device__ __forceinline__ void mma_f16(float* c, const uint32_t* a,
                                        const uint32_t* b) {
    asm volatile(
        "mma.sync.aligned.m16n8k16.row.col.f32.f16.f16.f32 "
        "{%0,%1,%2,%3}, {%4,%5,%6,%7}, {%8,%9}, {%0,%1,%2,%3};"
        : "+f"(c[0]), "+f"(c[1]), "+f"(c[2]), "+f"(c[3])
        : "r"(a[0]), "r"(a[1]), "r"(a[2]), "r"(a[3]), "r"(b[0]), "r"(b[1]));
}
__device__ __forceinline__ void split_store(int hl, int off, float v0, float v1) {
    __nv_bfloat16 h0 = __float2bfloat16_rn(v0);
    __nv_bfloat16 h1 = __float2bfloat16_rn(v1);
    __nv_bfloat16 l0 = __float2bfloat16_rn(v0 - __bfloat162float(h0));
    __nv_bfloat16 l1 = __float2bfloat16_rn(v1 - __bfloat162float(h1));
    *(uint32_t*)&g_bhi[hl][off] = bf2_pack(h0, h1);
    *(uint32_t*)&g_blo[hl][off] = bf2_pack(l0, l1);
}

// ======================= build kernels =====================================
// One CTA per row e: deg = max(sum |W[e,:]|, 1e-8), then emit N row (fp32 +
// hi/lo). Merges the old build_deg + build_N (saves a launch + global pass).
__global__ __launch_bounds__(256)
void build_degN(const float* __restrict__ W, const float* __restrict__ p) {
    __shared__ float red[8];
    const int e   = blockIdx.x;
    const int tid = threadIdx.x;
    const float* row = W + (size_t)e * DIM;

    float s = fabsf(row[tid]) + fabsf(row[tid + 256]);
    #pragma unroll
    for (int o = 16; o > 0; o >>= 1) s += __shfl_down_sync(0xffffffffu, s, o);
    if ((tid & 31) == 0) red[tid >> 5] = s;
    __syncthreads();
    if (tid == 0) {
        float t = 0.f;
        #pragma unroll
        for (int w = 0; w < 8; w++) t += red[w];
        red[0] = fmaxf(t, 1e-8f);
    }
    __syncthreads();
    const float dg = red[0];

    int d = tid * 2;
    int idx = e * DIM + d;
    float m0 = fabsf(row[d])     / dg;
    float m1 = fabsf(row[d + 1]) / dg;
    if (e == d)     m0 -= (1.1f + p[d]);
    if (e == d + 1) m1 -= (1.1f + p[d + 1]);
    g_buf[BUF_N][idx]     = m0;
    g_buf[BUF_N][idx + 1] = m1;
    split_store(HB_N, idx, m0, m1);
}

// h (fp32) -> fp16 (read by the big GEMM)
__global__ void split_h(const float* __restrict__ h, int nvec) {
    int v = blockIdx.x * blockDim.x + threadIdx.x;
    if (v >= nvec) return;
    float4 x = ((const float4*)h)[v];
    int idx = v * 4;
    __half2 a = __floats2half2_rn(x.x, x.y);
    __half2 b = __floats2half2_rn(x.z, x.w);
    *(uint2*)&g_hf[idx] = make_uint2(*(uint32_t*)&a, *(uint32_t*)&b);
}

__global__ __launch_bounds__(256)
void build_D(const float* __restrict__ p, Coef cf) {
    int v = blockIdx.x * blockDim.x + threadIdx.x;
    if (v >= DIM * DIM / 2) return;
    int idx = v * 2;
    int e = idx >> 9;
    int d = idx & (DIM - 1);
    float r[3][2];
    #pragma unroll
    for (int u = 0; u < 2; u++) {
        int dd = d + u;
        float x0 = (e == dd) ? 1.f : 0.f;
        float x1 = g_buf[BUF_N ][idx + u];
        float x2 = g_buf[BUF_N2][idx + u];
        float x3 = g_buf[BUF_N3][idx + u];
        float pd = p[dd];
        #pragma unroll
        for (int j = 0; j < 3; j++) {
            float vp = cf.P[j][0] * x0 + cf.P[j][1] * x1 + cf.P[j][2] * x2 + cf.P[j][3] * x3;
            float vq = cf.Q[j][0] * x0 + cf.Q[j][1] * x1 + cf.Q[j][2] * x2 + cf.Q[j][3] * x3;
            r[j][u] = vp + vq * pd;
        }
    }
    g_buf[BUF_D0][idx]     = r[0][0];
    g_buf[BUF_D0][idx + 1] = r[0][1];
    g_buf[BUF_D1][idx]     = r[1][0];
    g_buf[BUF_D1][idx + 1] = r[1][1];
    split_store(HB_D2, idx, r[2][0], r[2][1]);
}

// ======================= mma.sync 512^3 GEMM (BK=64, 4 warps) ==============
// C = A(hi/lo) @ B(hi/lo); CTA 32x64, grid (16,8,z), 128 threads / 4 warps,
// warp tile 32x16 (mt=2 x nt=2 -> 4 independent accumulators, 12 MMAs/k-step).
// B fragments via ldmatrix.x4.trans (one op covers k16 x n16).
// Dynamic smem layout (54KB) unchanged from R14.
#define M5_AHI 0
#define M5_ALO 9216
#define M5_BHI 18432
#define M5_BLO 36864
#define M5_TOT 55296
#define M5_ABUF 4608
#define M5_BBUF 9216
#define KPAD 72

__global__ __launch_bounds__(128, 1)
void mma512(Job j0, Job j1, const float* __restrict__ ga) {
    extern __shared__ char dsm[];
    const uint32_t sb = smem_u32(dsm);

    const Job j = (blockIdx.z == 0) ? j0 : j1;
    const int tid  = threadIdx.x;
    const int wc   = tid >> 5;        // 4 warps -> n quarter (16 cols)
    const int lane = tid & 31;
    const int brow = blockIdx.x * 32;
    const int bcol = blockIdx.y * 64;

    const __nv_bfloat16* __restrict__ Ah = g_bhi[j.ahl];
    const __nv_bfloat16* __restrict__ Al = g_blo[j.ahl];
    const __nv_bfloat16* __restrict__ Bh = g_bhi[j.bhl];
    const __nv_bfloat16* __restrict__ Bl = g_blo[j.bhl];

    float acc[2][2][4];
    #pragma unroll
    for (int mt = 0; mt < 2; mt++)
        #pragma unroll
        for (int nt = 0; nt < 2; nt++)
            #pragma unroll
            for (int q = 0; q < 4; q++) acc[mt][nt][q] = 0.f;

    const int aRowL = lane & 15;
    const int aKp   = (lane >> 4) * 8;
    // x4.trans B addressing: group g=lane>>3: row=(g&1)*8+(lane&7), col=(g>>1)*8
    const int bg   = lane >> 3;
    const int bro  = (bg & 1) * 8 + (lane & 7);
    const int bco  = wc * 16 + (bg >> 1) * 8;

    // prologue: chunk 0 -> buffer 0 (128 threads)
    #pragma unroll
    for (int i = 0; i < 2; i++) {
        int s = tid + i * 128;
        int lar = s >> 3, laq = s & 7;
        uint32_t ad = sb + (uint32_t)((lar * KPAD + laq * 8) * 2);
        cp16(ad + M5_AHI, &Ah[(size_t)(brow + lar) * DIM + laq * 8]);
        cp16(ad + M5_ALO, &Al[(size_t)(brow + lar) * DIM + laq * 8]);
    }
    #pragma unroll
    for (int i = 0; i < 4; i++) {
        int s = tid + i * 128;
        int br = s >> 3, bq = s & 7;
        uint32_t bd = sb + (uint32_t)((br * KPAD + bq * 8) * 2);
        cp16(bd + M5_BHI, &Bh[(size_t)br * DIM + bcol + bq * 8]);
        cp16(bd + M5_BLO, &Bl[(size_t)br * DIM + bcol + bq * 8]);
    }
    CP_COMMIT();

    for (int ch = 0; ch < 8; ch++) {
        if (ch + 1 < 8) {
            const int nb = (ch + 1) & 1;
            const int nk = (ch + 1) * 64;
            #pragma unroll
            for (int i = 0; i < 2; i++) {
                int s = tid + i * 128;
                int lar = s >> 3, laq = s & 7;
                uint32_t ad = sb + (uint32_t)(nb * M5_ABUF + (lar * KPAD + laq * 8) * 2);
                cp16(ad + M5_AHI, &Ah[(size_t)(brow + lar) * DIM + nk + laq * 8]);
                cp16(ad + M5_ALO, &Al[(size_t)(brow + lar) * DIM + nk + laq * 8]);
            }
            #pragma unroll
            for (int i = 0; i < 4; i++) {
                int s = tid + i * 128;
                int br = s >> 3, bq = s & 7;
                uint32_t bd = sb + (uint32_t)(nb * M5_BBUF + (br * KPAD + bq * 8) * 2);
                cp16(bd + M5_BHI, &Bh[(size_t)(nk + br) * DIM + bcol + bq * 8]);
                cp16(bd + M5_BLO, &Bl[(size_t)(nk + br) * DIM + bcol + bq * 8]);
            }
            CP_COMMIT();
            CP_WAIT1();
        } else {
            CP_WAIT0();
        }
        __syncthreads();

        const int pb = ch & 1;
        const uint32_t aBase = sb + (uint32_t)(pb * M5_ABUF);
        const uint32_t bBase = sb + (uint32_t)(pb * M5_BBUF);

        #pragma unroll
        for (int ks = 0; ks < 4; ks++) {
            const int kk = ks * 16;
            uint32_t ah[2][4], al[2][4], bh[4], bl[4];
            #pragma unroll
            for (int mt = 0; mt < 2; mt++) {
                uint32_t ao = ((uint32_t)((mt * 16 + aRowL) * KPAD + kk + aKp)) * 2;
                ldm_x4(ah[mt][0], ah[mt][1], ah[mt][2], ah[mt][3], aBase + M5_AHI + ao);
                ldm_x4(al[mt][0], al[mt][1], al[mt][2], al[mt][3], aBase + M5_ALO + ao);
            }
            {
                uint32_t bo = ((uint32_t)((kk + bro) * KPAD + bco)) * 2;
                ldm_x4t(bh[0], bh[1], bh[2], bh[3], bBase + M5_BHI + bo);
                ldm_x4t(bl[0], bl[1], bl[2], bl[3], bBase + M5_BLO + bo);
            }
            #pragma unroll
            for (int mt = 0; mt < 2; mt++)
                #pragma unroll
                for (int nt = 0; nt < 2; nt++) {
                    mma_bf16(acc[mt][nt], ah[mt], bh + nt * 2);
                    mma_bf16(acc[mt][nt], ah[mt], bl + nt * 2);
                    mma_bf16(acc[mt][nt], al[mt], bh + nt * 2);
                }
        }
        __syncthreads();
    }

    const float g = (j.mode == 2) ? tanhf(ga[0]) : 0.f;
    const float omg = 1.0f - g;
    const int er0 = brow + (lane >> 2);
    const int ec0 = bcol + wc * 16 + (lane & 3) * 2;

    #pragma unroll
    for (int mt = 0; mt < 2; mt++) {
        #pragma unroll
        for (int nt = 0; nt < 2; nt++) {
            #pragma unroll
            for (int half = 0; half < 2; half++) {
                int r = er0 + mt * 16 + half * 8;
                int c = ec0 + nt * 8;
                int off = r * DIM + c;
                float v0 = acc[mt][nt][half * 2 + 0];
                float v1 = acc[mt][nt][half * 2 + 1];
                if (j.mode == 1) {
                    v0 += g_buf[j.addi][off];
                    v1 += g_buf[j.addi][off + 1];
                } else if (j.mode == 2) {
                    v0 = g * (v0 + g_buf[j.addi][off])     + ((r == c)     ? omg : 0.f);
                    v1 = g * (v1 + g_buf[j.addi][off + 1]) + ((r == c + 1) ? omg : 0.f);
                }
                if (j.outfp >= 0) *(float2*)&g_buf[j.outfp][off] = make_float2(v0, v1);
                if (j.outhl >= 0) split_store(j.outhl, off, v0, v1);
                if (j.outf16) {
                    __half2 hv = __floats2half2_rn(v0, v1);
                    *(uint32_t*)&g_Hf[off] = *(uint32_t*)&hv;
                }
            }
        }
    }
}

// ======================= big GEMM: fp16, CTA 128x64, 2 CTAs/SM =============
// out[r, e] = sum_d h[r, d] * H[e, d]; A = g_hf, B = g_Hf (both fp16).
// CTA 128x64, grid (R/128, 8) = 1024 CTAs, 8 warps (2x4), warp 64x16, BK=64.
// Dynamic smem: As @0 (2 bufs x 128 x 72 fp16, stride 18432), Bs @36864
// (2 bufs x 64 x 72 fp16, stride 9216); total 55296 -> 2 CTAs/SM.
#define MG_AS   0
#define MG_BS   36864
#define MG_TOT  55296
#define MG_ABUF 18432
#define MG_BBUF 9216

__global__ __launch_bounds__(256, 2)
void mma_gemm3(float* __restrict__ out) {
    extern __shared__ char dsm[];
    const uint32_t sb = smem_u32(dsm);

    const int tid  = threadIdx.x;
    const int wid  = tid >> 5;
    const int lane = tid & 31;
    const int wr = wid & 1;          // 64-row half
    const int wc = wid >> 1;         // 16-col quarter
    const int brow = blockIdx.x * 128;
    const int bcol = blockIdx.y * 64;

    float acc[4][2][4];
    #pragma unroll
    for (int mt = 0; mt < 4; mt++)
        #pragma unroll
        for (int nt = 0; nt < 2; nt++)
            #pragma unroll
            for (int q = 0; q < 4; q++) acc[mt][nt][q] = 0.f;

    const int aRow = wr * 64 + (lane & 15);
    const int aKp  = (lane >> 4) * 8;
    const int bRow = wc * 16 + (lane & 7);
    const int bKp  = ((lane >> 3) & 1) * 8;

    // prologue (A: 1024 slots, 4/thread; B: 512 slots, 2/thread)
    #pragma unroll
    for (int i = 0; i < 4; i++) {
        int s = tid + i * 256;
        int row = s >> 3, q = s & 7;
        cp16(sb + MG_AS + (uint32_t)((row * KPAD + q * 8) * 2),
             &g_hf[(size_t)(brow + row) * DIM + q * 8]);
    }
    #pragma unroll
    for (int i = 0; i < 2; i++) {
        int s = tid + i * 256;
        int row = s >> 3, q = s & 7;
        cp16(sb + MG_BS + (uint32_t)((row * KPAD + q * 8) * 2),
             &g_Hf[(size_t)(bcol + row) * DIM + q * 8]);
    }
    CP_COMMIT();

    for (int ch = 0; ch < 8; ch++) {
        if (ch + 1 < 8) {
            const int nb = (ch + 1) & 1;
            const int nk = (ch + 1) * 64;
            #pragma unroll
            for (int i = 0; i < 4; i++) {
                int s = tid + i * 256;
                int row = s >> 3, q = s & 7;
                cp16(sb + MG_AS + (uint32_t)(nb * MG_ABUF + (row * KPAD + q * 8) * 2),
                     &g_hf[(size_t)(brow + row) * DIM + nk + q * 8]);
            }
            #pragma unroll
            for (int i = 0; i < 2; i++) {
                int s = tid + i * 256;
                int row = s >> 3, q = s & 7;
                cp16(sb + MG_BS + (uint32_t)(nb * MG_BBUF + (row * KPAD + q * 8) * 2),
                     &g_Hf[(size_t)(bcol + row) * DIM + nk + q * 8]);
            }
            CP_COMMIT();
            CP_WAIT1();
        } else {
            CP_WAIT0();
        }
        __syncthreads();

        const uint32_t aB = sb + MG_AS + (uint32_t)((ch & 1) * MG_ABUF);
        const uint32_t bB = sb + MG_BS + (uint32_t)((ch & 1) * MG_BBUF);

        #pragma unroll
        for (int ks = 0; ks < 4; ks++) {
            const int kk = ks * 16;
            uint32_t af[4][4], bf[2][2];
            #pragma unroll
            for (int mt = 0; mt < 4; mt++) {
                uint32_t ao = ((uint32_t)((aRow + mt * 16) * KPAD + kk + aKp)) * 2;
                ldm_x4(af[mt][0], af[mt][1], af[mt][2], af[mt][3], aB + ao);
            }
            #pragma unroll
            for (int nt = 0; nt < 2; nt++) {
                uint32_t bo = ((uint32_t)((bRow + nt * 8) * KPAD + kk + bKp)) * 2;
                ldm_x2(bf[nt][0], bf[nt][1], bB + bo);
            }
            #pragma unroll
            for (int mt = 0; mt < 4; mt++)
                #pragma unroll
                for (int nt = 0; nt < 2; nt++)
                    mma_f16(acc[mt][nt], af[mt], bf[nt]);
        }
        __syncthreads();
    }

    const int er = brow + wr * 64 + (lane >> 2);
    const int ec = bcol + wc * 16 + (lane & 3) * 2;
    #pragma unroll
    for (int mt = 0; mt < 4; mt++) {
        #pragma unroll
        for (int nt = 0; nt < 2; nt++) {
            float* p0 = out + (size_t)(er + mt * 16) * DIM + ec + nt * 8;
            *(float2*)p0 = make_float2(acc[mt][nt][0], acc[mt][nt][1]);
            float* p1 = out + (size_t)(er + mt * 16 + 8) * DIM + ec + nt * 8;
            *(float2*)p1 = make_float2(acc[mt][nt][2], acc[mt][nt][3]);
        }
    }
}

// ---------------------------------------------------------------------------
extern "C" void kernel_launch(void* const* d_in, const int* in_sizes, int n_in,
                              void* d_out, int out_size) {
    const float* h  = (const float*)d_in[0];
    const float* W  = (const float*)d_in[1];
    const float* ga = (const float*)d_in[2];
    const float* p  = (const float*)d_in[3];
    float* out = (float*)d_out;

    const int R = in_sizes[0] / DIM;          // B*S = 16384

    // host-side polynomial coefficients (doubles; deterministic)
    double Ac[12] = {0}, Bc[12] = {0}, Cc[12] = {0}, Dc[12] = {0};
    Ac[0] = 1.0;
    {
        const double dt = 0.1, beta = 2.0 * sqrt(2.1), c1 = 1.0 - dt * beta;
        for (int n = 0; n < 10; n++) {
            double Cn[12], Dn[12];
            for (int k = 0; k < 12; k++) {
                Cn[k] = c1 * Cc[k] + (k > 0 ? dt * Ac[k - 1] : 0.0);
                Dn[k] = c1 * Dc[k] + (k > 0 ? dt * Bc[k - 1] : 0.0);
            }
            Dn[0] += dt;
            for (int k = 0; k < 12; k++) {
                Cc[k] = Cn[k];  Dc[k] = Dn[k];
                Ac[k] += dt * Cn[k];
                Bc[k] += dt * Dn[k];
            }
        }
    }
    Coef cf;
    for (int j = 0; j < 3; j++)
        for (int m = 0; m < 4; m++) {
            cf.P[j][m] = (float)Ac[4 * j + m];
            cf.Q[j][m] = (float)Bc[4 * j + m];
        }

    const int PAIR_BLKS = (DIM * DIM / 2 + 255) / 256;
    const int HVEC = R * DIM / 4;

    cudaFuncSetAttribute(mma512, cudaFuncAttributeMaxDynamicSharedMemorySize, M5_TOT);
    cudaFuncSetAttribute(mma_gemm3, cudaFuncAttributeMaxDynamicSharedMemorySize, MG_TOT);

    build_degN<<<DIM, 256>>>(W, p);
    split_h<<<(HVEC + 255) / 256, 256>>>(h, HVEC);

    Job jN2 = {HB_N,  HB_N,  0, 0,      BUF_N2, HB_N2, 0};
    Job jN3 = {HB_N,  HB_N2, 0, 0,      BUF_N3, -1,    0};
    Job jN4 = {HB_N2, HB_N2, 0, 0,      -1,     HB_N4, 0};
    Job jE  = {HB_N4, HB_D2, 1, BUF_D1, -1,     HB_E,  0};
    Job jH  = {HB_N4, HB_E,  2, BUF_D0, -1,     -1,    1};

    mma512<<<dim3(16, 8, 1), 128, M5_TOT>>>(jN2, jN2, ga);   // N2
    mma512<<<dim3(16, 8, 2), 128, M5_TOT>>>(jN3, jN4, ga);   // N3 + N4
    build_D<<<PAIR_BLKS, 256>>>(p, cf);
    mma512<<<dim3(16, 8, 1), 128, M5_TOT>>>(jE, jE, ga);     // E = N4*D2 + D1
    mma512<<<dim3(16, 8, 1), 128, M5_TOT>>>(jH, jH, ga);     // H (emits fp16)

    mma_gemm3<<<dim3(R / 128, DIM / 64), 256, MG_TOT>>>(out);
}